// round 11
// baseline (speedup 1.0000x reference)
#include <cuda_runtime.h>
#include <cuda_bf16.h>
#include <cstdint>
#include <math.h>

#define B_  4
#define S_  2048
#define D_  1024
#define H_  16
#define DK_ 64
#define M_  (B_*S_)

// ---------------------------------------------------------------------------
// Scratch (__device__ globals). All tensors split bf16 hi + lo residual.
// ---------------------------------------------------------------------------
__device__ __nv_bfloat16 g_xh[(size_t)M_*D_];
__device__ __nv_bfloat16 g_xl[(size_t)M_*D_];
__device__ __nv_bfloat16 g_qh[(size_t)M_*D_];
__device__ __nv_bfloat16 g_ql[(size_t)M_*D_];
__device__ __nv_bfloat16 g_kh[(size_t)M_*D_];
__device__ __nv_bfloat16 g_kl[(size_t)M_*D_];
__device__ __nv_bfloat16 g_vh[(size_t)M_*D_];
__device__ __nv_bfloat16 g_vl[(size_t)M_*D_];
__device__ __nv_bfloat16 g_oh[(size_t)M_*D_];
__device__ __nv_bfloat16 g_ol[(size_t)M_*D_];

__device__ __nv_bfloat16 g_wqh[(size_t)D_*D_], g_wql[(size_t)D_*D_];
__device__ __nv_bfloat16 g_wkh[(size_t)D_*D_], g_wkl[(size_t)D_*D_];
__device__ __nv_bfloat16 g_wvh[(size_t)D_*D_], g_wvl[(size_t)D_*D_];
__device__ __nv_bfloat16 g_woh[(size_t)D_*D_], g_wol[(size_t)D_*D_];

// ---------------------------------------------------------------------------
// helpers
// ---------------------------------------------------------------------------
__device__ __forceinline__ void split2(float a, float b,
                                       __nv_bfloat162& h2, __nv_bfloat162& l2)
{
    h2.x = __float2bfloat16(a);
    h2.y = __float2bfloat16(b);
    l2.x = __float2bfloat16(a - __bfloat162float(h2.x));
    l2.y = __float2bfloat16(b - __bfloat162float(h2.y));
}

__device__ __forceinline__ void split_pack(float a, float b, uint32_t& hi, uint32_t& lo)
{
    __nv_bfloat162 h2, l2;
    split2(a, b, h2, l2);
    hi = *(uint32_t*)&h2;
    lo = *(uint32_t*)&l2;
}

__device__ __forceinline__ void ldsm4(uint32_t* r, uint32_t addr)
{
    asm volatile("ldmatrix.sync.aligned.m8n8.x4.shared.b16 {%0,%1,%2,%3}, [%4];"
        : "=r"(r[0]), "=r"(r[1]), "=r"(r[2]), "=r"(r[3]) : "r"(addr));
}

__device__ __forceinline__ void ldsm4t(uint32_t* r, uint32_t addr)
{
    asm volatile("ldmatrix.sync.aligned.m8n8.x4.trans.shared.b16 {%0,%1,%2,%3}, [%4];"
        : "=r"(r[0]), "=r"(r[1]), "=r"(r[2]), "=r"(r[3]) : "r"(addr));
}

__device__ __forceinline__ void mma16816(float* c, const uint32_t* a, const uint32_t* b)
{
    asm volatile("mma.sync.aligned.m16n8k16.row.col.f32.bf16.bf16.f32 "
        "{%0,%1,%2,%3}, {%4,%5,%6,%7}, {%8,%9}, {%0,%1,%2,%3};"
        : "+f"(c[0]), "+f"(c[1]), "+f"(c[2]), "+f"(c[3])
        : "r"(a[0]), "r"(a[1]), "r"(a[2]), "r"(a[3]), "r"(b[0]), "r"(b[1]));
}

__device__ __forceinline__ void cpasync16(uint32_t dst, const void* src)
{
    asm volatile("cp.async.cg.shared.global [%0], [%1], 16;" :: "r"(dst), "l"(src));
}

// ---------------------------------------------------------------------------
// Pack kernels: fp32 -> bf16 hi + lo
// ---------------------------------------------------------------------------
__device__ __forceinline__ void pack_body(const float* __restrict__ src,
                                          __nv_bfloat16* __restrict__ hi,
                                          __nv_bfloat16* __restrict__ lo,
                                          int blk)
{
    int i = (blk * 256 + threadIdx.x) * 4;
    float4 v = *(const float4*)(src + i);
    __nv_bfloat162 h0, l0, h1, l1;
    split2(v.x, v.y, h0, l0);
    split2(v.z, v.w, h1, l1);
    *(__nv_bfloat162*)(hi + i)     = h0;
    *(__nv_bfloat162*)(hi + i + 2) = h1;
    *(__nv_bfloat162*)(lo + i)     = l0;
    *(__nv_bfloat162*)(lo + i + 2) = l1;
}

__global__ __launch_bounds__(256) void pack_x_kernel(const float* __restrict__ s)
{ pack_body(s, g_xh, g_xl, blockIdx.x); }

__global__ __launch_bounds__(256) void pack_wo_kernel(const float* __restrict__ s)
{ pack_body(s, g_woh, g_wol, blockIdx.x); }

__global__ __launch_bounds__(256) void pack_wqkv_kernel(const float* __restrict__ wq,
                                                        const float* __restrict__ wk,
                                                        const float* __restrict__ wv)
{
    int which = blockIdx.x >> 10;
    int blk   = blockIdx.x & 1023;
    const float* src = (which == 0) ? wq : (which == 1) ? wk : wv;
    __nv_bfloat16* hi = (which == 0) ? g_wqh : (which == 1) ? g_wkh : g_wvh;
    __nv_bfloat16* lo = (which == 0) ? g_wql : (which == 1) ? g_wkl : g_wvl;
    pack_body(src, hi, lo, blk);
}

// ---------------------------------------------------------------------------
// Tensor-core GEMM (split bf16, 3-pass), BK=64 per mainloop iteration.
// 16 iterations cover K=1024. Structure mirrors the attention QK^T loop
// (192 HMMA between barrier pairs, padded stride-72 layout).
// 2 smem stages x 73.7KB -> 1 CTA/SM, 8 warps.
// ---------------------------------------------------------------------------
#define GS    72                    // stride in halves (64 data + 8 pad)
#define GARR  (128 * GS)            // halves per array (128 rows)
#define GSTG  (4 * GARR)            // halves per stage (Ah,Al,Bh,Bl)
#define GSM2  (2 * GSTG * 2)        // dynamic smem bytes: 147,456
#define GNKT  16                    // 16 x 64-K tiles over K=1024

template<int MODE>
__device__ __forceinline__ void gemm_tc(const __nv_bfloat16* __restrict__ Xh,
                                        const __nv_bfloat16* __restrict__ Xl,
                                        const __nv_bfloat16* __restrict__ Wh,
                                        const __nv_bfloat16* __restrict__ Wl,
                                        const float* __restrict__ bias,
                                        float* __restrict__ Yf,
                                        __nv_bfloat16* __restrict__ Yh,
                                        __nv_bfloat16* __restrict__ Yl,
                                        int row0, int col0)
{
    extern __shared__ __nv_bfloat16 smem[];

    const int tid  = threadIdx.x;
    const int lane = tid & 31;
    const int w    = tid >> 5;
    const int wm   = (w >> 2) * 64;
    const int wn   = (w & 3) * 32;

    float acc[4][4][4];
#pragma unroll
    for (int im = 0; im < 4; im++)
#pragma unroll
        for (int in = 0; in < 4; in++)
#pragma unroll
            for (int q = 0; q < 4; q++)
                acc[im][in][q] = 0.0f;

    const uint32_t aS = (uint32_t)__cvta_generic_to_shared(smem);

    // copy mapping: arr = tid>>6 (0:Ah 1:Al 2:Bh 3:Bl), rows rr and rr+64,
    // each row 128B (64 halves) per 64-K tile = 8 x 16B chunks.
    const int arr = tid >> 6;
    const int rr  = tid & 63;
    const __nv_bfloat16* gsrc = (arr == 0) ? Xh : (arr == 1) ? Xl
                               : (arr == 2) ? Wh : Wl;
    const int rbase = (arr < 2) ? row0 : col0;
    const __nv_bfloat16* s0 = gsrc + (size_t)(rbase + rr) * D_;
    const __nv_bfloat16* s1 = gsrc + (size_t)(rbase + rr + 64) * D_;
    const uint32_t dOff0 = (uint32_t)(arr * GARR + rr * GS) * 2;
    const uint32_t dOff1 = dOff0 + (uint32_t)(64 * GS) * 2;

#define ISSUE_COPY(stg, ktv)                                                   \
    do {                                                                       \
        uint32_t db0 = aS + (uint32_t)(stg) * (GSTG * 2) + dOff0;              \
        uint32_t db1 = aS + (uint32_t)(stg) * (GSTG * 2) + dOff1;              \
        const __nv_bfloat16* p0 = s0 + (ktv) * 64;                             \
        const __nv_bfloat16* p1 = s1 + (ktv) * 64;                             \
        _Pragma("unroll")                                                      \
        for (int c = 0; c < 8; c++) {                                          \
            cpasync16(db0 + c * 16, p0 + c * 8);                               \
            cpasync16(db1 + c * 16, p1 + c * 8);                               \
        }                                                                      \
        asm volatile("cp.async.commit_group;" ::: "memory");                   \
    } while (0)

    ISSUE_COPY(0, 0);

    for (int kt = 0; kt < GNKT; kt++) {         // 16 x 64-K = 1024
        const int s = kt & 1;
        asm volatile("cp.async.wait_group 0;" ::: "memory");
        __syncthreads();
        if (kt + 1 < GNKT)
            ISSUE_COPY(s ^ 1, kt + 1);

        const uint32_t bAh = aS + (uint32_t)s * (GSTG * 2);
        const uint32_t bAl = bAh + (uint32_t)GARR * 2;
        const uint32_t bBh = bAh + (uint32_t)(2 * GARR) * 2;
        const uint32_t bBl = bAh + (uint32_t)(3 * GARR) * 2;

#pragma unroll
        for (int t = 0; t < 4; t++) {           // four 16-K chunks
            const uint32_t colb = (uint32_t)(t * 16 + ((lane >> 4) << 3)) * 2;

            uint32_t bfh[4][2];
            uint32_t bfl[4][2];
#pragma unroll
            for (int np = 0; np < 2; np++) {
                uint32_t off = (uint32_t)((wn + np * 16 + (lane & 15)) * GS) * 2 + colb;
                uint32_t r4[4];
                ldsm4(r4, bBh + off);
                bfh[np * 2 + 0][0] = r4[0];
                bfh[np * 2 + 0][1] = r4[2];
                bfh[np * 2 + 1][0] = r4[1];
                bfh[np * 2 + 1][1] = r4[3];
                ldsm4(r4, bBl + off);
                bfl[np * 2 + 0][0] = r4[0];
                bfl[np * 2 + 0][1] = r4[2];
                bfl[np * 2 + 1][0] = r4[1];
                bfl[np * 2 + 1][1] = r4[3];
            }

#pragma unroll
            for (int im = 0; im < 4; im++) {
                uint32_t afh[4];
                uint32_t afl[4];
                uint32_t off = (uint32_t)((wm + im * 16 + (lane & 15)) * GS) * 2 + colb;
                ldsm4(afh, bAh + off);
                ldsm4(afl, bAl + off);
                // pass-major: consecutive mma target different accumulators;
                // per-accumulator order stays hh, hl, lh (K ascending).
#pragma unroll
                for (int in = 0; in < 4; in++)
                    mma16816(acc[im][in], afh, bfh[in]);
#pragma unroll
                for (int in = 0; in < 4; in++)
                    mma16816(acc[im][in], afh, bfl[in]);
#pragma unroll
                for (int in = 0; in < 4; in++)
                    mma16816(acc[im][in], afl, bfh[in]);
            }
        }
        __syncthreads();
    }
#undef ISSUE_COPY

    const int r_in = lane >> 2;
    const int c_in = (lane & 3) * 2;
#pragma unroll
    for (int im = 0; im < 4; im++) {
#pragma unroll
        for (int in = 0; in < 4; in++) {
            int rg = row0 + wm + im * 16 + r_in;
            int cg = col0 + wn + in * 8 + c_in;
            float b0 = bias[cg];
            float b1 = bias[cg + 1];
            float2 v0;
            float2 v1;
            v0.x = acc[im][in][0] + b0;
            v0.y = acc[im][in][1] + b1;
            v1.x = acc[im][in][2] + b0;
            v1.y = acc[im][in][3] + b1;
            if (MODE == 0) {
                *(float2*)(Yf + (size_t)rg * D_ + cg)       = v0;
                *(float2*)(Yf + (size_t)(rg + 8) * D_ + cg) = v1;
            } else {
                int hh = cg >> 6;
                int dd = cg & 63;
                int bb = rg >> 11;
                int ss = rg & (S_ - 1);
                size_t base = (((size_t)bb * H_ + hh) * S_ + ss) * DK_ + dd;
                __nv_bfloat162 h2, l2;
                split2(v0.x, v0.y, h2, l2);
                *(__nv_bfloat162*)(Yh + base) = h2;
                *(__nv_bfloat162*)(Yl + base) = l2;
                split2(v1.x, v1.y, h2, l2);
                *(__nv_bfloat162*)(Yh + base + 8 * DK_) = h2;
                *(__nv_bfloat162*)(Yl + base + 8 * DK_) = l2;
            }
        }
    }
}

// Fused Q/K/V projection: grid (24, 64); blockIdx.x>>3 selects the weight.
__global__ __launch_bounds__(256) void gemm_qkv_kernel(const float* __restrict__ bq,
                                                       const float* __restrict__ bk,
                                                       const float* __restrict__ bv)
{
    const int which = blockIdx.x >> 3;
    const int col0  = (blockIdx.x & 7) * 128;
    const int row0  = blockIdx.y * 128;
    const __nv_bfloat16* Wh = (which == 0) ? g_wqh : (which == 1) ? g_wkh : g_wvh;
    const __nv_bfloat16* Wl = (which == 0) ? g_wql : (which == 1) ? g_wkl : g_wvl;
    const float* bias       = (which == 0) ? bq    : (which == 1) ? bk    : bv;
    __nv_bfloat16* Yh       = (which == 0) ? g_qh  : (which == 1) ? g_kh  : g_vh;
    __nv_bfloat16* Yl       = (which == 0) ? g_ql  : (which == 1) ? g_kl  : g_vl;
    gemm_tc<1>(g_xh, g_xl, Wh, Wl, bias, nullptr, Yh, Yl, row0, col0);
}

__global__ __launch_bounds__(256) void gemm_o_kernel(const float* __restrict__ b,
                                                     float* __restrict__ out)
{
    gemm_tc<0>(g_oh, g_ol, g_woh, g_wol, b, out, nullptr, nullptr,
               blockIdx.y * 128, blockIdx.x * 128);
}

// ---------------------------------------------------------------------------
// Tensor-core flash attention (unchanged from round 8 — known good).
// ---------------------------------------------------------------------------
#define LDQ   72
#define AQH   0
#define AQL   (128*LDQ)
#define AKV0  (2*128*LDQ)
#define KVARR (64*LDQ)
#define KVST  (4*KVARR)
#define ASM_BYTES ((AKV0 + 2*KVST) * 2)

__global__ __launch_bounds__(256) void attn_kernel()
{
    extern __shared__ __nv_bfloat16 sm[];
    const int tid  = threadIdx.x;
    const int lane = tid & 31;
    const int w    = tid >> 5;
    const int bh   = blockIdx.y;
    const int qt   = blockIdx.x;
    const int q0   = qt * 128;
    const int wrow = w * 16;

    const size_t hb = (size_t)bh * S_ * DK_;
    const uint32_t aS = (uint32_t)__cvta_generic_to_shared(sm);

    {
        int a = tid >> 7;
        int r = tid & 127;
        const __nv_bfloat16* src = (a ? g_ql : g_qh) + hb + (size_t)(q0 + r) * DK_;
        uint32_t dst = aS + (uint32_t)((a ? AQL : AQH) + r * LDQ) * 2;
#pragma unroll
        for (int c = 0; c < 8; c++)
            cpasync16(dst + c * 16, src + c * 8);
    }

    const int kv_a = tid >> 6;
    const int kv_r = tid & 63;
    const __nv_bfloat16* kv_src =
        ((kv_a == 0) ? g_kh : (kv_a == 1) ? g_kl : (kv_a == 2) ? g_vh : g_vl)
        + hb + (size_t)kv_r * DK_;
    const uint32_t kv_doff = (uint32_t)(AKV0 + kv_a * KVARR + kv_r * LDQ) * 2;

#define ISSUE_KV(kt_, st_)                                                        \
    do {                                                                          \
        const __nv_bfloat16* sp = kv_src + (size_t)(kt_) * 64 * DK_;              \
        uint32_t dst = aS + kv_doff + (uint32_t)((st_) * KVST) * 2;               \
        _Pragma("unroll")                                                         \
        for (int c = 0; c < 8; c++)                                               \
            cpasync16(dst + c * 16, sp + c * 8);                                  \
        asm volatile("cp.async.commit_group;");                                   \
    } while (0)

    ISSUE_KV(0, 0);

    const int ktmax = 2 * qt + 1;

    float o[8][4];
#pragma unroll
    for (int j = 0; j < 8; j++)
#pragma unroll
        for (int q = 0; q < 4; q++)
            o[j][q] = 0.0f;
    float m0 = -INFINITY, m1 = -INFINITY, l0 = 0.0f, l1 = 0.0f;

    uint32_t qfh[4][4];
    uint32_t qfl[4][4];

    for (int kt = 0; kt <= ktmax; kt++) {
        const int st = kt & 1;
        asm volatile("cp.async.wait_group 0;");
        __syncthreads();
        if (kt < ktmax)
            ISSUE_KV(kt + 1, st ^ 1);

        if (kt == 0) {
#pragma unroll
            for (int t = 0; t < 4; t++) {
                uint32_t off = (uint32_t)((wrow + (lane & 15)) * LDQ
                                          + t * 16 + ((lane >> 4) << 3)) * 2;
                ldsm4(qfh[t], aS + (uint32_t)AQH * 2 + off);
                ldsm4(qfl[t], aS + (uint32_t)AQL * 2 + off);
            }
        }

        if (kt * 64 <= q0 + wrow + 15) {
            const uint32_t kvb = aS + (uint32_t)(AKV0 + st * KVST) * 2;

            float sf[8][4];
#pragma unroll
            for (int j = 0; j < 8; j++)
#pragma unroll
                for (int q = 0; q < 4; q++)
                    sf[j][q] = 0.0f;

#pragma unroll
            for (int t = 0; t < 4; t++) {
                const uint32_t colb = (uint32_t)(t * 16 + ((lane >> 4) << 3)) * 2;
#pragma unroll
                for (int nt = 0; nt < 4; nt++) {
                    uint32_t off = kvb + (uint32_t)((nt * 16 + (lane & 15)) * LDQ) * 2 + colb;
                    uint32_t r4[4];
                    uint32_t kh0[2], kh1[2], kl0[2], kl1[2];
                    ldsm4(r4, off);
                    kh0[0] = r4[0]; kh0[1] = r4[2];
                    kh1[0] = r4[1]; kh1[1] = r4[3];
                    ldsm4(r4, off + (uint32_t)KVARR * 2);
                    kl0[0] = r4[0]; kl0[1] = r4[2];
                    kl1[0] = r4[1]; kl1[1] = r4[3];
                    mma16816(sf[nt * 2],     qfh[t], kh0);
                    mma16816(sf[nt * 2 + 1], qfh[t], kh1);
                    mma16816(sf[nt * 2],     qfh[t], kl0);
                    mma16816(sf[nt * 2 + 1], qfh[t], kl1);
                    mma16816(sf[nt * 2],     qfl[t], kh0);
                    mma16816(sf[nt * 2 + 1], qfl[t], kh1);
                }
            }

#pragma unroll
            for (int j = 0; j < 8; j++)
#pragma unroll
                for (int q = 0; q < 4; q++)
                    sf[j][q] *= 0.125f;

            const int r0g = q0 + wrow + (lane >> 2);
            const int r1g = r0g + 8;
            if (kt * 64 + 63 > q0 + wrow) {
                const int cbase = kt * 64 + 2 * (lane & 3);
#pragma unroll
                for (int j = 0; j < 8; j++) {
                    int c = cbase + 8 * j;
                    if (c     > r0g) sf[j][0] = -INFINITY;
                    if (c + 1 > r0g) sf[j][1] = -INFINITY;
                    if (c     > r1g) sf[j][2] = -INFINITY;
                    if (c + 1 > r1g) sf[j][3] = -INFINITY;
                }
            }

            float rm0 = -INFINITY, rm1 = -INFINITY;
#pragma unroll
            for (int j = 0; j < 8; j++) {
                rm0 = fmaxf(rm0, fmaxf(sf[j][0], sf[j][1]));
                rm1 = fmaxf(rm1, fmaxf(sf[j][2], sf[j][3]));
            }
            rm0 = fmaxf(rm0, __shfl_xor_sync(0xffffffffu, rm0, 1));
            rm0 = fmaxf(rm0, __shfl_xor_sync(0xffffffffu, rm0, 2));
            rm1 = fmaxf(rm1, __shfl_xor_sync(0xffffffffu, rm1, 1));
            rm1 = fmaxf(rm1, __shfl_xor_sync(0xffffffffu, rm1, 2));

            float mn0 = fmaxf(m0, rm0);
            float mn1 = fmaxf(m1, rm1);
            float rs0 = 0.0f, rs1 = 0.0f;
#pragma unroll
            for (int j = 0; j < 8; j++) {
                sf[j][0] = __expf(sf[j][0] - mn0);
                sf[j][1] = __expf(sf[j][1] - mn0);
                sf[j][2] = __expf(sf[j][2] - mn1);
                sf[j][3] = __expf(sf[j][3] - mn1);
                rs0 += sf[j][0] + sf[j][1];
                rs1 += sf[j][2] + sf[j][3];
            }
            rs0 += __shfl_xor_sync(0xffffffffu, rs0, 1);
            rs0 += __shfl_xor_sync(0xffffffffu, rs0, 2);
            rs1 += __shfl_xor_sync(0xffffffffu, rs1, 1);
            rs1 += __shfl_xor_sync(0xffffffffu, rs1, 2);

            float a0 = __expf(m0 - mn0);
            float a1 = __expf(m1 - mn1);
            l0 = l0 * a0 + rs0;
            l1 = l1 * a1 + rs1;
            m0 = mn0;
            m1 = mn1;
#pragma unroll
            for (int j = 0; j < 8; j++) {
                o[j][0] *= a0;
                o[j][1] *= a0;
                o[j][2] *= a1;
                o[j][3] *= a1;
            }

            uint32_t pah[4][4];
            uint32_t pal[4][4];
#pragma unroll
            for (int t = 0; t < 4; t++) {
                split_pack(sf[2*t][0],   sf[2*t][1],   pah[t][0], pal[t][0]);
                split_pack(sf[2*t][2],   sf[2*t][3],   pah[t][1], pal[t][1]);
                split_pack(sf[2*t+1][0], sf[2*t+1][1], pah[t][2], pal[t][2]);
                split_pack(sf[2*t+1][2], sf[2*t+1][3], pah[t][3], pal[t][3]);
            }

#pragma unroll
            for (int t = 0; t < 4; t++) {
#pragma unroll
                for (int dt = 0; dt < 4; dt++) {
                    uint32_t off = kvb
                        + (uint32_t)((t * 16 + ((lane & 16) >> 1) + (lane & 7)) * LDQ
                                     + dt * 16 + (lane & 8)) * 2;
                    uint32_t r4[4];
                    uint32_t vh0[2], vh1[2], vl0[2], vl1[2];
                    ldsm4t(r4, off + (uint32_t)(2 * KVARR) * 2);
                    vh0[0] = r4[0]; vh0[1] = r4[2];
                    vh1[0] = r4[1]; vh1[1] = r4[3];
                    ldsm4t(r4, off + (uint32_t)(3 * KVARR) * 2);
                    vl0[0] = r4[0]; vl0[1] = r4[2];
                    vl1[0] = r4[1]; vl1[1] = r4[3];
                    mma16816(o[dt * 2],     pah[t], vh0);
                    mma16816(o[dt * 2 + 1], pah[t], vh1);
                    mma16816(o[dt * 2],     pah[t], vl0);
                    mma16816(o[dt * 2 + 1], pah[t], vl1);
                    mma16816(o[dt * 2],     pal[t], vh0);
                    mma16816(o[dt * 2 + 1], pal[t], vh1);
                }
            }
        }
    }
#undef ISSUE_KV

    const float in0 = 1.0f / l0;
    const float in1 = 1.0f / l1;
    const int r0 = q0 + wrow + (lane >> 2);
    const int bb = bh >> 4;
    const int hh = bh & 15;
#pragma unroll
    for (int j = 0; j < 8; j++) {
        int d = hh * 64 + j * 8 + 2 * (lane & 3);
        size_t i0 = ((size_t)bb * S_ + r0) * D_ + d;
        size_t i1 = i0 + (size_t)8 * D_;
        __nv_bfloat162 h2, l2;
        split2(o[j][0] * in0, o[j][1] * in0, h2, l2);
        *(__nv_bfloat162*)(g_oh + i0) = h2;
        *(__nv_bfloat162*)(g_ol + i0) = l2;
        split2(o[j][2] * in1, o[j][3] * in1, h2, l2);
        *(__nv_bfloat162*)(g_oh + i1) = h2;
        *(__nv_bfloat162*)(g_ol + i1) = l2;
    }
}

// ---------------------------------------------------------------------------
extern "C" void kernel_launch(void* const* d_in, const int* in_sizes, int n_in,
                              void* d_out, int out_size)
{
    const float* x  = (const float*)d_in[0];
    const float* Wq = (const float*)d_in[1];
    const float* bq = (const float*)d_in[2];
    const float* Wk = (const float*)d_in[3];
    const float* bk = (const float*)d_in[4];
    const float* Wv = (const float*)d_in[5];
    const float* bv = (const float*)d_in[6];
    const float* Wo = (const float*)d_in[7];
    const float* bo = (const float*)d_in[8];
    float* out = (float*)d_out;

    static int attr_set = 0;
    if (!attr_set) {
        cudaFuncSetAttribute(gemm_qkv_kernel, cudaFuncAttributeMaxDynamicSharedMemorySize, GSM2);
        cudaFuncSetAttribute(gemm_o_kernel,   cudaFuncAttributeMaxDynamicSharedMemorySize, GSM2);
        cudaFuncSetAttribute(attn_kernel,     cudaFuncAttributeMaxDynamicSharedMemorySize, ASM_BYTES);
        attr_set = 1;
    }

    pack_x_kernel   <<<(M_ * D_) / 1024, 256>>>(x);              // 0
    pack_wqkv_kernel<<<3 * (D_ * D_) / 1024, 256>>>(Wq, Wk, Wv); // 1
    pack_wo_kernel  <<<(D_ * D_) / 1024, 256>>>(Wo);             // 2

    gemm_qkv_kernel<<<dim3(24, 64), 256, GSM2>>>(bq, bk, bv);    // 3  <- ncu target

    attn_kernel<<<dim3(S_ / 128, B_ * H_), 256, ASM_BYTES>>>();  // 4

    gemm_o_kernel<<<dim3(8, 64), 256, GSM2>>>(bo, out);          // 5
}

// round 12
// speedup vs baseline: 1.2880x; 1.2880x over previous
#include <cuda_runtime.h>
#include <cuda_bf16.h>
#include <cstdint>
#include <math.h>

#define B_  4
#define S_  2048
#define D_  1024
#define H_  16
#define DK_ 64
#define M_  (B_*S_)

// ---------------------------------------------------------------------------
// Scratch (__device__ globals). All tensors split bf16 hi + lo residual.
// ---------------------------------------------------------------------------
__device__ __nv_bfloat16 g_xh[(size_t)M_*D_];
__device__ __nv_bfloat16 g_xl[(size_t)M_*D_];
__device__ __nv_bfloat16 g_qh[(size_t)M_*D_];
__device__ __nv_bfloat16 g_ql[(size_t)M_*D_];
__device__ __nv_bfloat16 g_kh[(size_t)M_*D_];
__device__ __nv_bfloat16 g_kl[(size_t)M_*D_];
__device__ __nv_bfloat16 g_vh[(size_t)M_*D_];
__device__ __nv_bfloat16 g_vl[(size_t)M_*D_];
__device__ __nv_bfloat16 g_oh[(size_t)M_*D_];
__device__ __nv_bfloat16 g_ol[(size_t)M_*D_];

__device__ __nv_bfloat16 g_wqh[(size_t)D_*D_], g_wql[(size_t)D_*D_];
__device__ __nv_bfloat16 g_wkh[(size_t)D_*D_], g_wkl[(size_t)D_*D_];
__device__ __nv_bfloat16 g_wvh[(size_t)D_*D_], g_wvl[(size_t)D_*D_];
__device__ __nv_bfloat16 g_woh[(size_t)D_*D_], g_wol[(size_t)D_*D_];

// ---------------------------------------------------------------------------
// helpers
// ---------------------------------------------------------------------------
__device__ __forceinline__ void split2(float a, float b,
                                       __nv_bfloat162& h2, __nv_bfloat162& l2)
{
    h2.x = __float2bfloat16(a);
    h2.y = __float2bfloat16(b);
    l2.x = __float2bfloat16(a - __bfloat162float(h2.x));
    l2.y = __float2bfloat16(b - __bfloat162float(h2.y));
}

__device__ __forceinline__ void split_pack(float a, float b, uint32_t& hi, uint32_t& lo)
{
    __nv_bfloat162 h2, l2;
    split2(a, b, h2, l2);
    hi = *(uint32_t*)&h2;
    lo = *(uint32_t*)&l2;
}

__device__ __forceinline__ void ldsm4(uint32_t* r, uint32_t addr)
{
    asm volatile("ldmatrix.sync.aligned.m8n8.x4.shared.b16 {%0,%1,%2,%3}, [%4];"
        : "=r"(r[0]), "=r"(r[1]), "=r"(r[2]), "=r"(r[3]) : "r"(addr));
}

__device__ __forceinline__ void ldsm4t(uint32_t* r, uint32_t addr)
{
    asm volatile("ldmatrix.sync.aligned.m8n8.x4.trans.shared.b16 {%0,%1,%2,%3}, [%4];"
        : "=r"(r[0]), "=r"(r[1]), "=r"(r[2]), "=r"(r[3]) : "r"(addr));
}

__device__ __forceinline__ void mma16816(float* c, const uint32_t* a, const uint32_t* b)
{
    asm volatile("mma.sync.aligned.m16n8k16.row.col.f32.bf16.bf16.f32 "
        "{%0,%1,%2,%3}, {%4,%5,%6,%7}, {%8,%9}, {%0,%1,%2,%3};"
        : "+f"(c[0]), "+f"(c[1]), "+f"(c[2]), "+f"(c[3])
        : "r"(a[0]), "r"(a[1]), "r"(a[2]), "r"(a[3]), "r"(b[0]), "r"(b[1]));
}

__device__ __forceinline__ void cpasync16(uint32_t dst, const void* src)
{
    asm volatile("cp.async.cg.shared.global [%0], [%1], 16;" :: "r"(dst), "l"(src));
}

// ---------------------------------------------------------------------------
// Pack kernels: fp32 -> bf16 hi + lo
// ---------------------------------------------------------------------------
__device__ __forceinline__ void pack_body(const float* __restrict__ src,
                                          __nv_bfloat16* __restrict__ hi,
                                          __nv_bfloat16* __restrict__ lo,
                                          int blk)
{
    int i = (blk * 256 + threadIdx.x) * 4;
    float4 v = *(const float4*)(src + i);
    __nv_bfloat162 h0, l0, h1, l1;
    split2(v.x, v.y, h0, l0);
    split2(v.z, v.w, h1, l1);
    *(__nv_bfloat162*)(hi + i)     = h0;
    *(__nv_bfloat162*)(hi + i + 2) = h1;
    *(__nv_bfloat162*)(lo + i)     = l0;
    *(__nv_bfloat162*)(lo + i + 2) = l1;
}

__global__ __launch_bounds__(256) void pack_x_kernel(const float* __restrict__ s)
{ pack_body(s, g_xh, g_xl, blockIdx.x); }

__global__ __launch_bounds__(256) void pack_wo_kernel(const float* __restrict__ s)
{ pack_body(s, g_woh, g_wol, blockIdx.x); }

// packs Wq, Wk, Wv in one launch: 1024 blocks each
__global__ __launch_bounds__(256) void pack_wqkv_kernel(const float* __restrict__ wq,
                                                        const float* __restrict__ wk,
                                                        const float* __restrict__ wv)
{
    int which = blockIdx.x >> 10;
    int blk   = blockIdx.x & 1023;
    const float* src = (which == 0) ? wq : (which == 1) ? wk : wv;
    __nv_bfloat16* hi = (which == 0) ? g_wqh : (which == 1) ? g_wkh : g_wvh;
    __nv_bfloat16* lo = (which == 0) ? g_wql : (which == 1) ? g_wkl : g_wvl;
    pack_body(src, hi, lo, blk);
}

// ---------------------------------------------------------------------------
// Tensor-core GEMM body (split bf16, 3-pass), cp.async double-buffered,
// BK=32, 2 CTAs/SM (80KB smem, reg cap 128). ONE barrier per k-tile: the
// trailing sync is redundant — iteration kt+1's copy into stage s is ordered
// after all compute on stage s by kt+1's top barrier.
// ---------------------------------------------------------------------------
#define GLDA 40
#define GT   (128 * GLDA)
#define GSM  (2 * 4 * GT * 2)

template<int MODE>
__device__ __forceinline__ void gemm_tc(const __nv_bfloat16* __restrict__ Xh,
                                        const __nv_bfloat16* __restrict__ Xl,
                                        const __nv_bfloat16* __restrict__ Wh,
                                        const __nv_bfloat16* __restrict__ Wl,
                                        const float* __restrict__ bias,
                                        float* __restrict__ Yf,
                                        __nv_bfloat16* __restrict__ Yh,
                                        __nv_bfloat16* __restrict__ Yl,
                                        int row0, int col0)
{
    extern __shared__ __nv_bfloat16 smem[];

    const int tid  = threadIdx.x;
    const int lane = tid & 31;
    const int w    = tid >> 5;
    const int wm   = (w >> 2) * 64;
    const int wn   = (w & 3) * 32;

    float acc[4][4][4];
#pragma unroll
    for (int im = 0; im < 4; im++)
#pragma unroll
        for (int in = 0; in < 4; in++)
#pragma unroll
            for (int q = 0; q < 4; q++)
                acc[im][in][q] = 0.0f;

    const uint32_t aS = (uint32_t)__cvta_generic_to_shared(smem);
    const int cr  = tid >> 2;
    const int cc8 = (tid & 3) * 8;

    const __nv_bfloat16* srcA_h = Xh + (size_t)(row0 + cr) * D_ + cc8;
    const __nv_bfloat16* srcA_l = Xl + (size_t)(row0 + cr) * D_ + cc8;
    const __nv_bfloat16* srcB_h = Wh + (size_t)(col0 + cr) * D_ + cc8;
    const __nv_bfloat16* srcB_l = Wl + (size_t)(col0 + cr) * D_ + cc8;
    const uint32_t dOff   = (uint32_t)(cr * GLDA + cc8) * 2;
    const uint32_t dRow64 = (uint32_t)(64 * GLDA) * 2;

#define ISSUE_COPY(sstage, k0v)                                                   \
    do {                                                                          \
        uint32_t db = aS + (uint32_t)((sstage) * 4 * GT) * 2 + dOff;              \
        cpasync16(db,                           srcA_h + (k0v));                  \
        cpasync16(db + dRow64,                  srcA_h + (k0v) + 64 * D_);        \
        cpasync16(db + (uint32_t)GT*2,          srcA_l + (k0v));                  \
        cpasync16(db + (uint32_t)GT*2 + dRow64, srcA_l + (k0v) + 64 * D_);        \
        cpasync16(db + (uint32_t)GT*4,          srcB_h + (k0v));                  \
        cpasync16(db + (uint32_t)GT*4 + dRow64, srcB_h + (k0v) + 64 * D_);        \
        cpasync16(db + (uint32_t)GT*6,          srcB_l + (k0v));                  \
        cpasync16(db + (uint32_t)GT*6 + dRow64, srcB_l + (k0v) + 64 * D_);        \
        asm volatile("cp.async.commit_group;");                                   \
    } while (0)

    ISSUE_COPY(0, 0);

    for (int kt = 0; kt < D_ / 32; kt++) {
        const int s = kt & 1;
        asm volatile("cp.async.wait_group 0;");
        __syncthreads();
        if (kt + 1 < D_ / 32)
            ISSUE_COPY(s ^ 1, (kt + 1) * 32);

        const uint32_t bAh = aS + (uint32_t)((s * 4 + 0) * GT) * 2;
        const uint32_t bAl = aS + (uint32_t)((s * 4 + 1) * GT) * 2;
        const uint32_t bBh = aS + (uint32_t)((s * 4 + 2) * GT) * 2;
        const uint32_t bBl = aS + (uint32_t)((s * 4 + 3) * GT) * 2;

#pragma unroll
        for (int kc = 0; kc < 2; kc++) {
            const uint32_t colb = (uint32_t)(kc * 16 + ((lane >> 4) << 3)) * 2;

            uint32_t bfh[4][2];
            uint32_t bfl[4][2];
#pragma unroll
            for (int np = 0; np < 2; np++) {
                uint32_t off = (uint32_t)((wn + np * 16 + (lane & 15)) * GLDA) * 2 + colb;
                uint32_t r4[4];
                ldsm4(r4, bBh + off);
                bfh[np * 2 + 0][0] = r4[0];
                bfh[np * 2 + 0][1] = r4[2];
                bfh[np * 2 + 1][0] = r4[1];
                bfh[np * 2 + 1][1] = r4[3];
                ldsm4(r4, bBl + off);
                bfl[np * 2 + 0][0] = r4[0];
                bfl[np * 2 + 0][1] = r4[2];
                bfl[np * 2 + 1][0] = r4[1];
                bfl[np * 2 + 1][1] = r4[3];
            }

#pragma unroll
            for (int im = 0; im < 4; im++) {
                uint32_t afh[4];
                uint32_t afl[4];
                uint32_t off = (uint32_t)((wm + im * 16 + (lane & 15)) * GLDA) * 2 + colb;
                ldsm4(afh, bAh + off);
                ldsm4(afl, bAl + off);
                // pass-major: consecutive mma target different accumulators;
                // per-accumulator order stays hh, hl, lh (K ascending).
#pragma unroll
                for (int in = 0; in < 4; in++)
                    mma16816(acc[im][in], afh, bfh[in]);
#pragma unroll
                for (int in = 0; in < 4; in++)
                    mma16816(acc[im][in], afh, bfl[in]);
#pragma unroll
                for (int in = 0; in < 4; in++)
                    mma16816(acc[im][in], afl, bfh[in]);
            }
        }
        // NOTE: no trailing __syncthreads — the next iteration's top barrier
        // orders all compute on stage s before any copy overwrites it.
    }
#undef ISSUE_COPY

    const int r_in = lane >> 2;
    const int c_in = (lane & 3) * 2;
#pragma unroll
    for (int im = 0; im < 4; im++) {
#pragma unroll
        for (int in = 0; in < 4; in++) {
            int rg = row0 + wm + im * 16 + r_in;
            int cg = col0 + wn + in * 8 + c_in;
            float b0 = bias[cg];
            float b1 = bias[cg + 1];
            float2 v0;
            float2 v1;
            v0.x = acc[im][in][0] + b0;
            v0.y = acc[im][in][1] + b1;
            v1.x = acc[im][in][2] + b0;
            v1.y = acc[im][in][3] + b1;
            if (MODE == 0) {
                *(float2*)(Yf + (size_t)rg * D_ + cg)       = v0;
                *(float2*)(Yf + (size_t)(rg + 8) * D_ + cg) = v1;
            } else {
                int hh = cg >> 6;
                int dd = cg & 63;
                int bb = rg >> 11;
                int ss = rg & (S_ - 1);
                size_t base = (((size_t)bb * H_ + hh) * S_ + ss) * DK_ + dd;
                __nv_bfloat162 h2, l2;
                split2(v0.x, v0.y, h2, l2);
                *(__nv_bfloat162*)(Yh + base) = h2;
                *(__nv_bfloat162*)(Yl + base) = l2;
                split2(v1.x, v1.y, h2, l2);
                *(__nv_bfloat162*)(Yh + base + 8 * DK_) = h2;
                *(__nv_bfloat162*)(Yl + base + 8 * DK_) = l2;
            }
        }
    }
}

// Fused Q/K/V projection: grid (24, 64); blockIdx.x>>3 selects the weight.
__global__ __launch_bounds__(256, 2) void gemm_qkv_kernel(const float* __restrict__ bq,
                                                          const float* __restrict__ bk,
                                                          const float* __restrict__ bv)
{
    const int which = blockIdx.x >> 3;
    const int col0  = (blockIdx.x & 7) * 128;
    const int row0  = blockIdx.y * 128;
    const __nv_bfloat16* Wh = (which == 0) ? g_wqh : (which == 1) ? g_wkh : g_wvh;
    const __nv_bfloat16* Wl = (which == 0) ? g_wql : (which == 1) ? g_wkl : g_wvl;
    const float* bias       = (which == 0) ? bq    : (which == 1) ? bk    : bv;
    __nv_bfloat16* Yh       = (which == 0) ? g_qh  : (which == 1) ? g_kh  : g_vh;
    __nv_bfloat16* Yl       = (which == 0) ? g_ql  : (which == 1) ? g_kl  : g_vl;
    gemm_tc<1>(g_xh, g_xl, Wh, Wl, bias, nullptr, Yh, Yl, row0, col0);
}

__global__ __launch_bounds__(256, 2) void gemm_o_kernel(const float* __restrict__ b,
                                                        float* __restrict__ out)
{
    gemm_tc<0>(g_oh, g_ol, g_woh, g_wol, b, out, nullptr, nullptr,
               blockIdx.y * 128, blockIdx.x * 128);
}

// ---------------------------------------------------------------------------
// Tensor-core flash attention (unchanged from round 8 — known good).
// ---------------------------------------------------------------------------
#define LDQ   72
#define AQH   0
#define AQL   (128*LDQ)
#define AKV0  (2*128*LDQ)
#define KVARR (64*LDQ)
#define KVST  (4*KVARR)
#define ASM_BYTES ((AKV0 + 2*KVST) * 2)

__global__ __launch_bounds__(256) void attn_kernel()
{
    extern __shared__ __nv_bfloat16 sm[];
    const int tid  = threadIdx.x;
    const int lane = tid & 31;
    const int w    = tid >> 5;
    const int bh   = blockIdx.y;
    const int qt   = blockIdx.x;
    const int q0   = qt * 128;
    const int wrow = w * 16;

    const size_t hb = (size_t)bh * S_ * DK_;
    const uint32_t aS = (uint32_t)__cvta_generic_to_shared(sm);

    {
        int a = tid >> 7;
        int r = tid & 127;
        const __nv_bfloat16* src = (a ? g_ql : g_qh) + hb + (size_t)(q0 + r) * DK_;
        uint32_t dst = aS + (uint32_t)((a ? AQL : AQH) + r * LDQ) * 2;
#pragma unroll
        for (int c = 0; c < 8; c++)
            cpasync16(dst + c * 16, src + c * 8);
    }

    const int kv_a = tid >> 6;
    const int kv_r = tid & 63;
    const __nv_bfloat16* kv_src =
        ((kv_a == 0) ? g_kh : (kv_a == 1) ? g_kl : (kv_a == 2) ? g_vh : g_vl)
        + hb + (size_t)kv_r * DK_;
    const uint32_t kv_doff = (uint32_t)(AKV0 + kv_a * KVARR + kv_r * LDQ) * 2;

#define ISSUE_KV(kt_, st_)                                                        \
    do {                                                                          \
        const __nv_bfloat16* sp = kv_src + (size_t)(kt_) * 64 * DK_;              \
        uint32_t dst = aS + kv_doff + (uint32_t)((st_) * KVST) * 2;               \
        _Pragma("unroll")                                                         \
        for (int c = 0; c < 8; c++)                                               \
            cpasync16(dst + c * 16, sp + c * 8);                                  \
        asm volatile("cp.async.commit_group;");                                   \
    } while (0)

    ISSUE_KV(0, 0);

    const int ktmax = 2 * qt + 1;

    float o[8][4];
#pragma unroll
    for (int j = 0; j < 8; j++)
#pragma unroll
        for (int q = 0; q < 4; q++)
            o[j][q] = 0.0f;
    float m0 = -INFINITY, m1 = -INFINITY, l0 = 0.0f, l1 = 0.0f;

    uint32_t qfh[4][4];
    uint32_t qfl[4][4];

    for (int kt = 0; kt <= ktmax; kt++) {
        const int st = kt & 1;
        asm volatile("cp.async.wait_group 0;");
        __syncthreads();
        if (kt < ktmax)
            ISSUE_KV(kt + 1, st ^ 1);

        if (kt == 0) {
#pragma unroll
            for (int t = 0; t < 4; t++) {
                uint32_t off = (uint32_t)((wrow + (lane & 15)) * LDQ
                                          + t * 16 + ((lane >> 4) << 3)) * 2;
                ldsm4(qfh[t], aS + (uint32_t)AQH * 2 + off);
                ldsm4(qfl[t], aS + (uint32_t)AQL * 2 + off);
            }
        }

        if (kt * 64 <= q0 + wrow + 15) {
            const uint32_t kvb = aS + (uint32_t)(AKV0 + st * KVST) * 2;

            float sf[8][4];
#pragma unroll
            for (int j = 0; j < 8; j++)
#pragma unroll
                for (int q = 0; q < 4; q++)
                    sf[j][q] = 0.0f;

#pragma unroll
            for (int t = 0; t < 4; t++) {
                const uint32_t colb = (uint32_t)(t * 16 + ((lane >> 4) << 3)) * 2;
#pragma unroll
                for (int nt = 0; nt < 4; nt++) {
                    uint32_t off = kvb + (uint32_t)((nt * 16 + (lane & 15)) * LDQ) * 2 + colb;
                    uint32_t r4[4];
                    uint32_t kh0[2], kh1[2], kl0[2], kl1[2];
                    ldsm4(r4, off);
                    kh0[0] = r4[0]; kh0[1] = r4[2];
                    kh1[0] = r4[1]; kh1[1] = r4[3];
                    ldsm4(r4, off + (uint32_t)KVARR * 2);
                    kl0[0] = r4[0]; kl0[1] = r4[2];
                    kl1[0] = r4[1]; kl1[1] = r4[3];
                    mma16816(sf[nt * 2],     qfh[t], kh0);
                    mma16816(sf[nt * 2 + 1], qfh[t], kh1);
                    mma16816(sf[nt * 2],     qfh[t], kl0);
                    mma16816(sf[nt * 2 + 1], qfh[t], kl1);
                    mma16816(sf[nt * 2],     qfl[t], kh0);
                    mma16816(sf[nt * 2 + 1], qfl[t], kh1);
                }
            }

#pragma unroll
            for (int j = 0; j < 8; j++)
#pragma unroll
                for (int q = 0; q < 4; q++)
                    sf[j][q] *= 0.125f;

            const int r0g = q0 + wrow + (lane >> 2);
            const int r1g = r0g + 8;
            if (kt * 64 + 63 > q0 + wrow) {
                const int cbase = kt * 64 + 2 * (lane & 3);
#pragma unroll
                for (int j = 0; j < 8; j++) {
                    int c = cbase + 8 * j;
                    if (c     > r0g) sf[j][0] = -INFINITY;
                    if (c + 1 > r0g) sf[j][1] = -INFINITY;
                    if (c     > r1g) sf[j][2] = -INFINITY;
                    if (c + 1 > r1g) sf[j][3] = -INFINITY;
                }
            }

            float rm0 = -INFINITY, rm1 = -INFINITY;
#pragma unroll
            for (int j = 0; j < 8; j++) {
                rm0 = fmaxf(rm0, fmaxf(sf[j][0], sf[j][1]));
                rm1 = fmaxf(rm1, fmaxf(sf[j][2], sf[j][3]));
            }
            rm0 = fmaxf(rm0, __shfl_xor_sync(0xffffffffu, rm0, 1));
            rm0 = fmaxf(rm0, __shfl_xor_sync(0xffffffffu, rm0, 2));
            rm1 = fmaxf(rm1, __shfl_xor_sync(0xffffffffu, rm1, 1));
            rm1 = fmaxf(rm1, __shfl_xor_sync(0xffffffffu, rm1, 2));

            float mn0 = fmaxf(m0, rm0);
            float mn1 = fmaxf(m1, rm1);
            float rs0 = 0.0f, rs1 = 0.0f;
#pragma unroll
            for (int j = 0; j < 8; j++) {
                sf[j][0] = __expf(sf[j][0] - mn0);
                sf[j][1] = __expf(sf[j][1] - mn0);
                sf[j][2] = __expf(sf[j][2] - mn1);
                sf[j][3] = __expf(sf[j][3] - mn1);
                rs0 += sf[j][0] + sf[j][1];
                rs1 += sf[j][2] + sf[j][3];
            }
            rs0 += __shfl_xor_sync(0xffffffffu, rs0, 1);
            rs0 += __shfl_xor_sync(0xffffffffu, rs0, 2);
            rs1 += __shfl_xor_sync(0xffffffffu, rs1, 1);
            rs1 += __shfl_xor_sync(0xffffffffu, rs1, 2);

            float a0 = __expf(m0 - mn0);
            float a1 = __expf(m1 - mn1);
            l0 = l0 * a0 + rs0;
            l1 = l1 * a1 + rs1;
            m0 = mn0;
            m1 = mn1;
#pragma unroll
            for (int j = 0; j < 8; j++) {
                o[j][0] *= a0;
                o[j][1] *= a0;
                o[j][2] *= a1;
                o[j][3] *= a1;
            }

            uint32_t pah[4][4];
            uint32_t pal[4][4];
#pragma unroll
            for (int t = 0; t < 4; t++) {
                split_pack(sf[2*t][0],   sf[2*t][1],   pah[t][0], pal[t][0]);
                split_pack(sf[2*t][2],   sf[2*t][3],   pah[t][1], pal[t][1]);
                split_pack(sf[2*t+1][0], sf[2*t+1][1], pah[t][2], pal[t][2]);
                split_pack(sf[2*t+1][2], sf[2*t+1][3], pah[t][3], pal[t][3]);
            }

#pragma unroll
            for (int t = 0; t < 4; t++) {
#pragma unroll
                for (int dt = 0; dt < 4; dt++) {
                    uint32_t off = kvb
                        + (uint32_t)((t * 16 + ((lane & 16) >> 1) + (lane & 7)) * LDQ
                                     + dt * 16 + (lane & 8)) * 2;
                    uint32_t r4[4];
                    uint32_t vh0[2], vh1[2], vl0[2], vl1[2];
                    ldsm4t(r4, off + (uint32_t)(2 * KVARR) * 2);
                    vh0[0] = r4[0]; vh0[1] = r4[2];
                    vh1[0] = r4[1]; vh1[1] = r4[3];
                    ldsm4t(r4, off + (uint32_t)(3 * KVARR) * 2);
                    vl0[0] = r4[0]; vl0[1] = r4[2];
                    vl1[0] = r4[1]; vl1[1] = r4[3];
                    mma16816(o[dt * 2],     pah[t], vh0);
                    mma16816(o[dt * 2 + 1], pah[t], vh1);
                    mma16816(o[dt * 2],     pah[t], vl0);
                    mma16816(o[dt * 2 + 1], pah[t], vl1);
                    mma16816(o[dt * 2],     pal[t], vh0);
                    mma16816(o[dt * 2 + 1], pal[t], vh1);
                }
            }
        }
    }
#undef ISSUE_KV

    const float in0 = 1.0f / l0;
    const float in1 = 1.0f / l1;
    const int r0 = q0 + wrow + (lane >> 2);
    const int bb = bh >> 4;
    const int hh = bh & 15;
#pragma unroll
    for (int j = 0; j < 8; j++) {
        int d = hh * 64 + j * 8 + 2 * (lane & 3);
        size_t i0 = ((size_t)bb * S_ + r0) * D_ + d;
        size_t i1 = i0 + (size_t)8 * D_;
        __nv_bfloat162 h2, l2;
        split2(o[j][0] * in0, o[j][1] * in0, h2, l2);
        *(__nv_bfloat162*)(g_oh + i0) = h2;
        *(__nv_bfloat162*)(g_ol + i0) = l2;
        split2(o[j][2] * in1, o[j][3] * in1, h2, l2);
        *(__nv_bfloat162*)(g_oh + i1) = h2;
        *(__nv_bfloat162*)(g_ol + i1) = l2;
    }
}

// ---------------------------------------------------------------------------
extern "C" void kernel_launch(void* const* d_in, const int* in_sizes, int n_in,
                              void* d_out, int out_size)
{
    const float* x  = (const float*)d_in[0];
    const float* Wq = (const float*)d_in[1];
    const float* bq = (const float*)d_in[2];
    const float* Wk = (const float*)d_in[3];
    const float* bk = (const float*)d_in[4];
    const float* Wv = (const float*)d_in[5];
    const float* bv = (const float*)d_in[6];
    const float* Wo = (const float*)d_in[7];
    const float* bo = (const float*)d_in[8];
    float* out = (float*)d_out;

    static int attr_set = 0;
    if (!attr_set) {
        cudaFuncSetAttribute(gemm_qkv_kernel, cudaFuncAttributeMaxDynamicSharedMemorySize, GSM);
        cudaFuncSetAttribute(gemm_o_kernel,   cudaFuncAttributeMaxDynamicSharedMemorySize, GSM);
        cudaFuncSetAttribute(attn_kernel,     cudaFuncAttributeMaxDynamicSharedMemorySize, ASM_BYTES);
        attr_set = 1;
    }

    pack_x_kernel   <<<(M_ * D_) / 1024, 256>>>(x);              // 0
    pack_wqkv_kernel<<<3 * (D_ * D_) / 1024, 256>>>(Wq, Wk, Wv); // 1
    pack_wo_kernel  <<<(D_ * D_) / 1024, 256>>>(Wo);             // 2

    gemm_qkv_kernel<<<dim3(24, 64), 256, GSM>>>(bq, bk, bv);     // 3  <- ncu target

    attn_kernel<<<dim3(S_ / 128, B_ * H_), 256, ASM_BYTES>>>();  // 4

    gemm_o_kernel<<<dim3(8, 64), 256, GSM>>>(bo, out);           // 5
}

// round 14
// speedup vs baseline: 1.3002x; 1.0094x over previous
#include <cuda_runtime.h>
#include <cuda_bf16.h>
#include <cstdint>
#include <math.h>

#define B_  4
#define S_  2048
#define D_  1024
#define H_  16
#define DK_ 64
#define M_  (B_*S_)

// ---------------------------------------------------------------------------
// Scratch (__device__ globals). All tensors split bf16 hi + lo residual.
// ---------------------------------------------------------------------------
__device__ __nv_bfloat16 g_xh[(size_t)M_*D_];
__device__ __nv_bfloat16 g_xl[(size_t)M_*D_];
__device__ __nv_bfloat16 g_qh[(size_t)M_*D_];
__device__ __nv_bfloat16 g_ql[(size_t)M_*D_];
__device__ __nv_bfloat16 g_kh[(size_t)M_*D_];
__device__ __nv_bfloat16 g_kl[(size_t)M_*D_];
__device__ __nv_bfloat16 g_vh[(size_t)M_*D_];
__device__ __nv_bfloat16 g_vl[(size_t)M_*D_];
__device__ __nv_bfloat16 g_oh[(size_t)M_*D_];
__device__ __nv_bfloat16 g_ol[(size_t)M_*D_];

__device__ __nv_bfloat16 g_wqh[(size_t)D_*D_], g_wql[(size_t)D_*D_];
__device__ __nv_bfloat16 g_wkh[(size_t)D_*D_], g_wkl[(size_t)D_*D_];
__device__ __nv_bfloat16 g_wvh[(size_t)D_*D_], g_wvl[(size_t)D_*D_];
__device__ __nv_bfloat16 g_woh[(size_t)D_*D_], g_wol[(size_t)D_*D_];

// ---------------------------------------------------------------------------
// helpers
// ---------------------------------------------------------------------------
__device__ __forceinline__ void split2(float a, float b,
                                       __nv_bfloat162& h2, __nv_bfloat162& l2)
{
    h2.x = __float2bfloat16(a);
    h2.y = __float2bfloat16(b);
    l2.x = __float2bfloat16(a - __bfloat162float(h2.x));
    l2.y = __float2bfloat16(b - __bfloat162float(h2.y));
}

__device__ __forceinline__ void split_pack(float a, float b, uint32_t& hi, uint32_t& lo)
{
    __nv_bfloat162 h2, l2;
    split2(a, b, h2, l2);
    hi = *(uint32_t*)&h2;
    lo = *(uint32_t*)&l2;
}

__device__ __forceinline__ void ldsm4(uint32_t* r, uint32_t addr)
{
    asm volatile("ldmatrix.sync.aligned.m8n8.x4.shared.b16 {%0,%1,%2,%3}, [%4];"
        : "=r"(r[0]), "=r"(r[1]), "=r"(r[2]), "=r"(r[3]) : "r"(addr));
}

__device__ __forceinline__ void ldsm4t(uint32_t* r, uint32_t addr)
{
    asm volatile("ldmatrix.sync.aligned.m8n8.x4.trans.shared.b16 {%0,%1,%2,%3}, [%4];"
        : "=r"(r[0]), "=r"(r[1]), "=r"(r[2]), "=r"(r[3]) : "r"(addr));
}

__device__ __forceinline__ void mma16816(float* c, const uint32_t* a, const uint32_t* b)
{
    asm volatile("mma.sync.aligned.m16n8k16.row.col.f32.bf16.bf16.f32 "
        "{%0,%1,%2,%3}, {%4,%5,%6,%7}, {%8,%9}, {%0,%1,%2,%3};"
        : "+f"(c[0]), "+f"(c[1]), "+f"(c[2]), "+f"(c[3])
        : "r"(a[0]), "r"(a[1]), "r"(a[2]), "r"(a[3]), "r"(b[0]), "r"(b[1]));
}

__device__ __forceinline__ void cpasync16(uint32_t dst, const void* src)
{
    asm volatile("cp.async.cg.shared.global [%0], [%1], 16;" :: "r"(dst), "l"(src));
}

// ---------------------------------------------------------------------------
// Pack kernels: fp32 -> bf16 hi + lo
// ---------------------------------------------------------------------------
__device__ __forceinline__ void pack_body(const float* __restrict__ src,
                                          __nv_bfloat16* __restrict__ hi,
                                          __nv_bfloat16* __restrict__ lo,
                                          int blk)
{
    int i = (blk * 256 + threadIdx.x) * 4;
    float4 v = *(const float4*)(src + i);
    __nv_bfloat162 h0, l0, h1, l1;
    split2(v.x, v.y, h0, l0);
    split2(v.z, v.w, h1, l1);
    *(__nv_bfloat162*)(hi + i)     = h0;
    *(__nv_bfloat162*)(hi + i + 2) = h1;
    *(__nv_bfloat162*)(lo + i)     = l0;
    *(__nv_bfloat162*)(lo + i + 2) = l1;
}

__global__ __launch_bounds__(256) void pack_x_kernel(const float* __restrict__ s)
{ pack_body(s, g_xh, g_xl, blockIdx.x); }

// packs Wq, Wk, Wv, Wo in one launch: 1024 blocks each (4096 total)
__global__ __launch_bounds__(256) void pack_w4_kernel(const float* __restrict__ wq,
                                                      const float* __restrict__ wk,
                                                      const float* __restrict__ wv,
                                                      const float* __restrict__ wo)
{
    int which = blockIdx.x >> 10;
    int blk   = blockIdx.x & 1023;
    const float* src = (which == 0) ? wq : (which == 1) ? wk : (which == 2) ? wv : wo;
    __nv_bfloat16* hi = (which == 0) ? g_wqh : (which == 1) ? g_wkh
                       : (which == 2) ? g_wvh : g_woh;
    __nv_bfloat16* lo = (which == 0) ? g_wql : (which == 1) ? g_wkl
                       : (which == 2) ? g_wvl : g_wol;
    pack_body(src, hi, lo, blk);
}

// ---------------------------------------------------------------------------
// Tensor-core GEMM body (split bf16, 3-pass), cp.async double-buffered,
// BK=32, 2 CTAs/SM (80KB smem, reg cap 128), one barrier per k-tile.
// ---------------------------------------------------------------------------
#define GLDA 40
#define GT   (128 * GLDA)
#define GSM  (2 * 4 * GT * 2)

template<int MODE>
__device__ __forceinline__ void gemm_tc(const __nv_bfloat16* __restrict__ Xh,
                                        const __nv_bfloat16* __restrict__ Xl,
                                        const __nv_bfloat16* __restrict__ Wh,
                                        const __nv_bfloat16* __restrict__ Wl,
                                        const float* __restrict__ bias,
                                        float* __restrict__ Yf,
                                        __nv_bfloat16* __restrict__ Yh,
                                        __nv_bfloat16* __restrict__ Yl,
                                        int row0, int col0)
{
    extern __shared__ __nv_bfloat16 smem[];

    const int tid  = threadIdx.x;
    const int lane = tid & 31;
    const int w    = tid >> 5;
    const int wm   = (w >> 2) * 64;
    const int wn   = (w & 3) * 32;

    float acc[4][4][4];
#pragma unroll
    for (int im = 0; im < 4; im++)
#pragma unroll
        for (int in = 0; in < 4; in++)
#pragma unroll
            for (int q = 0; q < 4; q++)
                acc[im][in][q] = 0.0f;

    const uint32_t aS = (uint32_t)__cvta_generic_to_shared(smem);
    const int cr  = tid >> 2;
    const int cc8 = (tid & 3) * 8;

    const __nv_bfloat16* srcA_h = Xh + (size_t)(row0 + cr) * D_ + cc8;
    const __nv_bfloat16* srcA_l = Xl + (size_t)(row0 + cr) * D_ + cc8;
    const __nv_bfloat16* srcB_h = Wh + (size_t)(col0 + cr) * D_ + cc8;
    const __nv_bfloat16* srcB_l = Wl + (size_t)(col0 + cr) * D_ + cc8;
    const uint32_t dOff   = (uint32_t)(cr * GLDA + cc8) * 2;
    const uint32_t dRow64 = (uint32_t)(64 * GLDA) * 2;

#define ISSUE_COPY(sstage, k0v)                                                   \
    do {                                                                          \
        uint32_t db = aS + (uint32_t)((sstage) * 4 * GT) * 2 + dOff;              \
        cpasync16(db,                           srcA_h + (k0v));                  \
        cpasync16(db + dRow64,                  srcA_h + (k0v) + 64 * D_);        \
        cpasync16(db + (uint32_t)GT*2,          srcA_l + (k0v));                  \
        cpasync16(db + (uint32_t)GT*2 + dRow64, srcA_l + (k0v) + 64 * D_);        \
        cpasync16(db + (uint32_t)GT*4,          srcB_h + (k0v));                  \
        cpasync16(db + (uint32_t)GT*4 + dRow64, srcB_h + (k0v) + 64 * D_);        \
        cpasync16(db + (uint32_t)GT*6,          srcB_l + (k0v));                  \
        cpasync16(db + (uint32_t)GT*6 + dRow64, srcB_l + (k0v) + 64 * D_);        \
        asm volatile("cp.async.commit_group;");                                   \
    } while (0)

    ISSUE_COPY(0, 0);

    for (int kt = 0; kt < D_ / 32; kt++) {
        const int s = kt & 1;
        asm volatile("cp.async.wait_group 0;");
        __syncthreads();
        if (kt + 1 < D_ / 32)
            ISSUE_COPY(s ^ 1, (kt + 1) * 32);

        const uint32_t bAh = aS + (uint32_t)((s * 4 + 0) * GT) * 2;
        const uint32_t bAl = aS + (uint32_t)((s * 4 + 1) * GT) * 2;
        const uint32_t bBh = aS + (uint32_t)((s * 4 + 2) * GT) * 2;
        const uint32_t bBl = aS + (uint32_t)((s * 4 + 3) * GT) * 2;

#pragma unroll
        for (int kc = 0; kc < 2; kc++) {
            const uint32_t colb = (uint32_t)(kc * 16 + ((lane >> 4) << 3)) * 2;

            uint32_t bfh[4][2];
            uint32_t bfl[4][2];
#pragma unroll
            for (int np = 0; np < 2; np++) {
                uint32_t off = (uint32_t)((wn + np * 16 + (lane & 15)) * GLDA) * 2 + colb;
                uint32_t r4[4];
                ldsm4(r4, bBh + off);
                bfh[np * 2 + 0][0] = r4[0];
                bfh[np * 2 + 0][1] = r4[2];
                bfh[np * 2 + 1][0] = r4[1];
                bfh[np * 2 + 1][1] = r4[3];
                ldsm4(r4, bBl + off);
                bfl[np * 2 + 0][0] = r4[0];
                bfl[np * 2 + 0][1] = r4[2];
                bfl[np * 2 + 1][0] = r4[1];
                bfl[np * 2 + 1][1] = r4[3];
            }

#pragma unroll
            for (int im = 0; im < 4; im++) {
                uint32_t afh[4];
                uint32_t afl[4];
                uint32_t off = (uint32_t)((wm + im * 16 + (lane & 15)) * GLDA) * 2 + colb;
                ldsm4(afh, bAh + off);
                ldsm4(afl, bAl + off);
                // pass-major: consecutive mma target different accumulators;
                // per-accumulator order stays hh, hl, lh (K ascending).
#pragma unroll
                for (int in = 0; in < 4; in++)
                    mma16816(acc[im][in], afh, bfh[in]);
#pragma unroll
                for (int in = 0; in < 4; in++)
                    mma16816(acc[im][in], afh, bfl[in]);
#pragma unroll
                for (int in = 0; in < 4; in++)
                    mma16816(acc[im][in], afl, bfh[in]);
            }
        }
        // no trailing __syncthreads — next iteration's top barrier orders
        // all compute on stage s before any copy overwrites it.
    }
#undef ISSUE_COPY

    const int r_in = lane >> 2;
    const int c_in = (lane & 3) * 2;
#pragma unroll
    for (int im = 0; im < 4; im++) {
#pragma unroll
        for (int in = 0; in < 4; in++) {
            int rg = row0 + wm + im * 16 + r_in;
            int cg = col0 + wn + in * 8 + c_in;
            float b0 = bias[cg];
            float b1 = bias[cg + 1];
            float2 v0;
            float2 v1;
            v0.x = acc[im][in][0] + b0;
            v0.y = acc[im][in][1] + b1;
            v1.x = acc[im][in][2] + b0;
            v1.y = acc[im][in][3] + b1;
            if (MODE == 0) {
                *(float2*)(Yf + (size_t)rg * D_ + cg)       = v0;
                *(float2*)(Yf + (size_t)(rg + 8) * D_ + cg) = v1;
            } else {
                int hh = cg >> 6;
                int dd = cg & 63;
                int bb = rg >> 11;
                int ss = rg & (S_ - 1);
                size_t base = (((size_t)bb * H_ + hh) * S_ + ss) * DK_ + dd;
                __nv_bfloat162 h2, l2;
                split2(v0.x, v0.y, h2, l2);
                *(__nv_bfloat162*)(Yh + base) = h2;
                *(__nv_bfloat162*)(Yl + base) = l2;
                split2(v1.x, v1.y, h2, l2);
                *(__nv_bfloat162*)(Yh + base + 8 * DK_) = h2;
                *(__nv_bfloat162*)(Yl + base + 8 * DK_) = l2;
            }
        }
    }
}

// Fused Q/K/V projection: grid (24, 64); blockIdx.x>>3 selects the weight.
__global__ __launch_bounds__(256, 2) void gemm_qkv_kernel(const float* __restrict__ bq,
                                                          const float* __restrict__ bk,
                                                          const float* __restrict__ bv)
{
    const int which = blockIdx.x >> 3;
    const int col0  = (blockIdx.x & 7) * 128;
    const int row0  = blockIdx.y * 128;
    const __nv_bfloat16* Wh = (which == 0) ? g_wqh : (which == 1) ? g_wkh : g_wvh;
    const __nv_bfloat16* Wl = (which == 0) ? g_wql : (which == 1) ? g_wkl : g_wvl;
    const float* bias       = (which == 0) ? bq    : (which == 1) ? bk    : bv;
    __nv_bfloat16* Yh       = (which == 0) ? g_qh  : (which == 1) ? g_kh  : g_vh;
    __nv_bfloat16* Yl       = (which == 0) ? g_ql  : (which == 1) ? g_kl  : g_vl;
    gemm_tc<1>(g_xh, g_xl, Wh, Wl, bias, nullptr, Yh, Yl, row0, col0);
}

__global__ __launch_bounds__(256, 2) void gemm_o_kernel(const float* __restrict__ b,
                                                        float* __restrict__ out)
{
    gemm_tc<0>(g_oh, g_ol, g_woh, g_wol, b, out, nullptr, nullptr,
               blockIdx.y * 128, blockIdx.x * 128);
}

// ---------------------------------------------------------------------------
// Tensor-core flash attention. Identical math to round 8; ONLY change:
// longest-first scheduling — qt = gridDim.x-1-blockIdx.x so the causal
// long-tail blocks (large qt, work ∝ qt+1) launch in the first wave.
// ---------------------------------------------------------------------------
#define LDQ   72
#define AQH   0
#define AQL   (128*LDQ)
#define AKV0  (2*128*LDQ)
#define KVARR (64*LDQ)
#define KVST  (4*KVARR)
#define ASM_BYTES ((AKV0 + 2*KVST) * 2)

__global__ __launch_bounds__(256) void attn_kernel()
{
    extern __shared__ __nv_bfloat16 sm[];
    const int tid  = threadIdx.x;
    const int lane = tid & 31;
    const int w    = tid >> 5;
    const int bh   = blockIdx.y;
    const int qt   = gridDim.x - 1 - blockIdx.x;   // longest-first
    const int q0   = qt * 128;
    const int wrow = w * 16;

    const size_t hb = (size_t)bh * S_ * DK_;
    const uint32_t aS = (uint32_t)__cvta_generic_to_shared(sm);

    {
        int a = tid >> 7;
        int r = tid & 127;
        const __nv_bfloat16* src = (a ? g_ql : g_qh) + hb + (size_t)(q0 + r) * DK_;
        uint32_t dst = aS + (uint32_t)((a ? AQL : AQH) + r * LDQ) * 2;
#pragma unroll
        for (int c = 0; c < 8; c++)
            cpasync16(dst + c * 16, src + c * 8);
    }

    const int kv_a = tid >> 6;
    const int kv_r = tid & 63;
    const __nv_bfloat16* kv_src =
        ((kv_a == 0) ? g_kh : (kv_a == 1) ? g_kl : (kv_a == 2) ? g_vh : g_vl)
        + hb + (size_t)kv_r * DK_;
    const uint32_t kv_doff = (uint32_t)(AKV0 + kv_a * KVARR + kv_r * LDQ) * 2;

#define ISSUE_KV(kt_, st_)                                                        \
    do {                                                                          \
        const __nv_bfloat16* sp = kv_src + (size_t)(kt_) * 64 * DK_;              \
        uint32_t dst = aS + kv_doff + (uint32_t)((st_) * KVST) * 2;               \
        _Pragma("unroll")                                                         \
        for (int c = 0; c < 8; c++)                                               \
            cpasync16(dst + c * 16, sp + c * 8);                                  \
        asm volatile("cp.async.commit_group;");                                   \
    } while (0)

    ISSUE_KV(0, 0);

    const int ktmax = 2 * qt + 1;

    float o[8][4];
#pragma unroll
    for (int j = 0; j < 8; j++)
#pragma unroll
        for (int q = 0; q < 4; q++)
            o[j][q] = 0.0f;
    float m0 = -INFINITY, m1 = -INFINITY, l0 = 0.0f, l1 = 0.0f;

    uint32_t qfh[4][4];
    uint32_t qfl[4][4];

    for (int kt = 0; kt <= ktmax; kt++) {
        const int st = kt & 1;
        asm volatile("cp.async.wait_group 0;");
        __syncthreads();
        if (kt < ktmax)
            ISSUE_KV(kt + 1, st ^ 1);

        if (kt == 0) {
#pragma unroll
            for (int t = 0; t < 4; t++) {
                uint32_t off = (uint32_t)((wrow + (lane & 15)) * LDQ
                                          + t * 16 + ((lane >> 4) << 3)) * 2;
                ldsm4(qfh[t], aS + (uint32_t)AQH * 2 + off);
                ldsm4(qfl[t], aS + (uint32_t)AQL * 2 + off);
            }
        }

        if (kt * 64 <= q0 + wrow + 15) {
            const uint32_t kvb = aS + (uint32_t)(AKV0 + st * KVST) * 2;

            float sf[8][4];
#pragma unroll
            for (int j = 0; j < 8; j++)
#pragma unroll
                for (int q = 0; q < 4; q++)
                    sf[j][q] = 0.0f;

#pragma unroll
            for (int t = 0; t < 4; t++) {
                const uint32_t colb = (uint32_t)(t * 16 + ((lane >> 4) << 3)) * 2;
#pragma unroll
                for (int nt = 0; nt < 4; nt++) {
                    uint32_t off = kvb + (uint32_t)((nt * 16 + (lane & 15)) * LDQ) * 2 + colb;
                    uint32_t r4[4];
                    uint32_t kh0[2], kh1[2], kl0[2], kl1[2];
                    ldsm4(r4, off);
                    kh0[0] = r4[0]; kh0[1] = r4[2];
                    kh1[0] = r4[1]; kh1[1] = r4[3];
                    ldsm4(r4, off + (uint32_t)KVARR * 2);
                    kl0[0] = r4[0]; kl0[1] = r4[2];
                    kl1[0] = r4[1]; kl1[1] = r4[3];
                    mma16816(sf[nt * 2],     qfh[t], kh0);
                    mma16816(sf[nt * 2 + 1], qfh[t], kh1);
                    mma16816(sf[nt * 2],     qfh[t], kl0);
                    mma16816(sf[nt * 2 + 1], qfh[t], kl1);
                    mma16816(sf[nt * 2],     qfl[t], kh0);
                    mma16816(sf[nt * 2 + 1], qfl[t], kh1);
                }
            }

#pragma unroll
            for (int j = 0; j < 8; j++)
#pragma unroll
                for (int q = 0; q < 4; q++)
                    sf[j][q] *= 0.125f;

            const int r0g = q0 + wrow + (lane >> 2);
            const int r1g = r0g + 8;
            if (kt * 64 + 63 > q0 + wrow) {
                const int cbase = kt * 64 + 2 * (lane & 3);
#pragma unroll
                for (int j = 0; j < 8; j++) {
                    int c = cbase + 8 * j;
                    if (c     > r0g) sf[j][0] = -INFINITY;
                    if (c + 1 > r0g) sf[j][1] = -INFINITY;
                    if (c     > r1g) sf[j][2] = -INFINITY;
                    if (c + 1 > r1g) sf[j][3] = -INFINITY;
                }
            }

            float rm0 = -INFINITY, rm1 = -INFINITY;
#pragma unroll
            for (int j = 0; j < 8; j++) {
                rm0 = fmaxf(rm0, fmaxf(sf[j][0], sf[j][1]));
                rm1 = fmaxf(rm1, fmaxf(sf[j][2], sf[j][3]));
            }
            rm0 = fmaxf(rm0, __shfl_xor_sync(0xffffffffu, rm0, 1));
            rm0 = fmaxf(rm0, __shfl_xor_sync(0xffffffffu, rm0, 2));
            rm1 = fmaxf(rm1, __shfl_xor_sync(0xffffffffu, rm1, 1));
            rm1 = fmaxf(rm1, __shfl_xor_sync(0xffffffffu, rm1, 2));

            float mn0 = fmaxf(m0, rm0);
            float mn1 = fmaxf(m1, rm1);
            float rs0 = 0.0f, rs1 = 0.0f;
#pragma unroll
            for (int j = 0; j < 8; j++) {
                sf[j][0] = __expf(sf[j][0] - mn0);
                sf[j][1] = __expf(sf[j][1] - mn0);
                sf[j][2] = __expf(sf[j][2] - mn1);
                sf[j][3] = __expf(sf[j][3] - mn1);
                rs0 += sf[j][0] + sf[j][1];
                rs1 += sf[j][2] + sf[j][3];
            }
            rs0 += __shfl_xor_sync(0xffffffffu, rs0, 1);
            rs0 += __shfl_xor_sync(0xffffffffu, rs0, 2);
            rs1 += __shfl_xor_sync(0xffffffffu, rs1, 1);
            rs1 += __shfl_xor_sync(0xffffffffu, rs1, 2);

            float a0 = __expf(m0 - mn0);
            float a1 = __expf(m1 - mn1);
            l0 = l0 * a0 + rs0;
            l1 = l1 * a1 + rs1;
            m0 = mn0;
            m1 = mn1;
#pragma unroll
            for (int j = 0; j < 8; j++) {
                o[j][0] *= a0;
                o[j][1] *= a0;
                o[j][2] *= a1;
                o[j][3] *= a1;
            }

            uint32_t pah[4][4];
            uint32_t pal[4][4];
#pragma unroll
            for (int t = 0; t < 4; t++) {
                split_pack(sf[2*t][0],   sf[2*t][1],   pah[t][0], pal[t][0]);
                split_pack(sf[2*t][2],   sf[2*t][3],   pah[t][1], pal[t][1]);
                split_pack(sf[2*t+1][0], sf[2*t+1][1], pah[t][2], pal[t][2]);
                split_pack(sf[2*t+1][2], sf[2*t+1][3], pah[t][3], pal[t][3]);
            }

#pragma unroll
            for (int t = 0; t < 4; t++) {
#pragma unroll
                for (int dt = 0; dt < 4; dt++) {
                    uint32_t off = kvb
                        + (uint32_t)((t * 16 + ((lane & 16) >> 1) + (lane & 7)) * LDQ
                                     + dt * 16 + (lane & 8)) * 2;
                    uint32_t r4[4];
                    uint32_t vh0[2], vh1[2], vl0[2], vl1[2];
                    ldsm4t(r4, off + (uint32_t)(2 * KVARR) * 2);
                    vh0[0] = r4[0]; vh0[1] = r4[2];
                    vh1[0] = r4[1]; vh1[1] = r4[3];
                    ldsm4t(r4, off + (uint32_t)(3 * KVARR) * 2);
                    vl0[0] = r4[0]; vl0[1] = r4[2];
                    vl1[0] = r4[1]; vl1[1] = r4[3];
                    mma16816(o[dt * 2],     pah[t], vh0);
                    mma16816(o[dt * 2 + 1], pah[t], vh1);
                    mma16816(o[dt * 2],     pah[t], vl0);
                    mma16816(o[dt * 2 + 1], pah[t], vl1);
                    mma16816(o[dt * 2],     pal[t], vh0);
                    mma16816(o[dt * 2 + 1], pal[t], vh1);
                }
            }
        }
    }
#undef ISSUE_KV

    const float in0 = 1.0f / l0;
    const float in1 = 1.0f / l1;
    const int r0 = q0 + wrow + (lane >> 2);
    const int bb = bh >> 4;
    const int hh = bh & 15;
#pragma unroll
    for (int j = 0; j < 8; j++) {
        int d = hh * 64 + j * 8 + 2 * (lane & 3);
        size_t i0 = ((size_t)bb * S_ + r0) * D_ + d;
        size_t i1 = i0 + (size_t)8 * D_;
        __nv_bfloat162 h2, l2;
        split2(o[j][0] * in0, o[j][1] * in0, h2, l2);
        *(__nv_bfloat162*)(g_oh + i0) = h2;
        *(__nv_bfloat162*)(g_ol + i0) = l2;
        split2(o[j][2] * in1, o[j][3] * in1, h2, l2);
        *(__nv_bfloat162*)(g_oh + i1) = h2;
        *(__nv_bfloat162*)(g_ol + i1) = l2;
    }
}

// ---------------------------------------------------------------------------
extern "C" void kernel_launch(void* const* d_in, const int* in_sizes, int n_in,
                              void* d_out, int out_size)
{
    const float* x  = (const float*)d_in[0];
    const float* Wq = (const float*)d_in[1];
    const float* bq = (const float*)d_in[2];
    const float* Wk = (const float*)d_in[3];
    const float* bk = (const float*)d_in[4];
    const float* Wv = (const float*)d_in[5];
    const float* bv = (const float*)d_in[6];
    const float* Wo = (const float*)d_in[7];
    const float* bo = (const float*)d_in[8];
    float* out = (float*)d_out;

    static int attr_set = 0;
    if (!attr_set) {
        cudaFuncSetAttribute(gemm_qkv_kernel, cudaFuncAttributeMaxDynamicSharedMemorySize, GSM);
        cudaFuncSetAttribute(gemm_o_kernel,   cudaFuncAttributeMaxDynamicSharedMemorySize, GSM);
        cudaFuncSetAttribute(attn_kernel,     cudaFuncAttributeMaxDynamicSharedMemorySize, ASM_BYTES);
        attr_set = 1;
    }

    pack_x_kernel <<<(M_ * D_) / 1024, 256>>>(x);                   // 0
    pack_w4_kernel<<<4 * (D_ * D_) / 1024, 256>>>(Wq, Wk, Wv, Wo);  // 1

    gemm_qkv_kernel<<<dim3(24, 64), 256, GSM>>>(bq, bk, bv);        // 2

    attn_kernel<<<dim3(S_ / 128, B_ * H_), 256, ASM_BYTES>>>();     // 3  <- ncu target

    gemm_o_kernel<<<dim3(8, 64), 256, GSM>>>(bo, out);              // 4
}

// round 15
// speedup vs baseline: 1.3657x; 1.0504x over previous
#include <cuda_runtime.h>
#include <cuda_bf16.h>
#include <cstdint>
#include <math.h>

#define B_  4
#define S_  2048
#define D_  1024
#define H_  16
#define DK_ 64
#define M_  (B_*S_)

// ---------------------------------------------------------------------------
// Scratch (__device__ globals). All tensors split bf16 hi + lo residual.
// ---------------------------------------------------------------------------
__device__ __nv_bfloat16 g_xh[(size_t)M_*D_];
__device__ __nv_bfloat16 g_xl[(size_t)M_*D_];
__device__ __nv_bfloat16 g_qh[(size_t)M_*D_];
__device__ __nv_bfloat16 g_ql[(size_t)M_*D_];
__device__ __nv_bfloat16 g_kh[(size_t)M_*D_];
__device__ __nv_bfloat16 g_kl[(size_t)M_*D_];
__device__ __nv_bfloat16 g_vh[(size_t)M_*D_];
__device__ __nv_bfloat16 g_vl[(size_t)M_*D_];
__device__ __nv_bfloat16 g_oh[(size_t)M_*D_];
__device__ __nv_bfloat16 g_ol[(size_t)M_*D_];

__device__ __nv_bfloat16 g_wqh[(size_t)D_*D_], g_wql[(size_t)D_*D_];
__device__ __nv_bfloat16 g_wkh[(size_t)D_*D_], g_wkl[(size_t)D_*D_];
__device__ __nv_bfloat16 g_wvh[(size_t)D_*D_], g_wvl[(size_t)D_*D_];
__device__ __nv_bfloat16 g_woh[(size_t)D_*D_], g_wol[(size_t)D_*D_];

// ---------------------------------------------------------------------------
// helpers
// ---------------------------------------------------------------------------
__device__ __forceinline__ void split2(float a, float b,
                                       __nv_bfloat162& h2, __nv_bfloat162& l2)
{
    h2.x = __float2bfloat16(a);
    h2.y = __float2bfloat16(b);
    l2.x = __float2bfloat16(a - __bfloat162float(h2.x));
    l2.y = __float2bfloat16(b - __bfloat162float(h2.y));
}

__device__ __forceinline__ void split_pack(float a, float b, uint32_t& hi, uint32_t& lo)
{
    __nv_bfloat162 h2, l2;
    split2(a, b, h2, l2);
    hi = *(uint32_t*)&h2;
    lo = *(uint32_t*)&l2;
}

__device__ __forceinline__ void ldsm4(uint32_t* r, uint32_t addr)
{
    asm volatile("ldmatrix.sync.aligned.m8n8.x4.shared.b16 {%0,%1,%2,%3}, [%4];"
        : "=r"(r[0]), "=r"(r[1]), "=r"(r[2]), "=r"(r[3]) : "r"(addr));
}

__device__ __forceinline__ void ldsm4t(uint32_t* r, uint32_t addr)
{
    asm volatile("ldmatrix.sync.aligned.m8n8.x4.trans.shared.b16 {%0,%1,%2,%3}, [%4];"
        : "=r"(r[0]), "=r"(r[1]), "=r"(r[2]), "=r"(r[3]) : "r"(addr));
}

__device__ __forceinline__ void mma16816(float* c, const uint32_t* a, const uint32_t* b)
{
    asm volatile("mma.sync.aligned.m16n8k16.row.col.f32.bf16.bf16.f32 "
        "{%0,%1,%2,%3}, {%4,%5,%6,%7}, {%8,%9}, {%0,%1,%2,%3};"
        : "+f"(c[0]), "+f"(c[1]), "+f"(c[2]), "+f"(c[3])
        : "r"(a[0]), "r"(a[1]), "r"(a[2]), "r"(a[3]), "r"(b[0]), "r"(b[1]));
}

__device__ __forceinline__ void cpasync16(uint32_t dst, const void* src)
{
    asm volatile("cp.async.cg.shared.global [%0], [%1], 16;" :: "r"(dst), "l"(src));
}

// ---------------------------------------------------------------------------
// Pack kernels: fp32 -> bf16 hi + lo
// ---------------------------------------------------------------------------
__device__ __forceinline__ void pack_body(const float* __restrict__ src,
                                          __nv_bfloat16* __restrict__ hi,
                                          __nv_bfloat16* __restrict__ lo,
                                          int blk)
{
    int i = (blk * 256 + threadIdx.x) * 4;
    float4 v = *(const float4*)(src + i);
    __nv_bfloat162 h0, l0, h1, l1;
    split2(v.x, v.y, h0, l0);
    split2(v.z, v.w, h1, l1);
    *(__nv_bfloat162*)(hi + i)     = h0;
    *(__nv_bfloat162*)(hi + i + 2) = h1;
    *(__nv_bfloat162*)(lo + i)     = l0;
    *(__nv_bfloat162*)(lo + i + 2) = l1;
}

__global__ __launch_bounds__(256) void pack_x_kernel(const float* __restrict__ s)
{ pack_body(s, g_xh, g_xl, blockIdx.x); }

// packs Wq, Wk, Wv, Wo in one launch: 1024 blocks each (4096 total)
__global__ __launch_bounds__(256) void pack_w4_kernel(const float* __restrict__ wq,
                                                      const float* __restrict__ wk,
                                                      const float* __restrict__ wv,
                                                      const float* __restrict__ wo)
{
    int which = blockIdx.x >> 10;
    int blk   = blockIdx.x & 1023;
    const float* src = (which == 0) ? wq : (which == 1) ? wk : (which == 2) ? wv : wo;
    __nv_bfloat16* hi = (which == 0) ? g_wqh : (which == 1) ? g_wkh
                       : (which == 2) ? g_wvh : g_woh;
    __nv_bfloat16* lo = (which == 0) ? g_wql : (which == 1) ? g_wkl
                       : (which == 2) ? g_wvl : g_wol;
    pack_body(src, hi, lo, blk);
}

// ---------------------------------------------------------------------------
// Tensor-core GEMM body (split bf16, 3-pass), cp.async double-buffered,
// BK=32, 2 CTAs/SM (80KB smem, reg cap 128), one barrier per k-tile.
// ---------------------------------------------------------------------------
#define GLDA 40
#define GT   (128 * GLDA)
#define GSM  (2 * 4 * GT * 2)

template<int MODE>
__device__ __forceinline__ void gemm_tc(const __nv_bfloat16* __restrict__ Xh,
                                        const __nv_bfloat16* __restrict__ Xl,
                                        const __nv_bfloat16* __restrict__ Wh,
                                        const __nv_bfloat16* __restrict__ Wl,
                                        const float* __restrict__ bias,
                                        float* __restrict__ Yf,
                                        __nv_bfloat16* __restrict__ Yh,
                                        __nv_bfloat16* __restrict__ Yl,
                                        int row0, int col0)
{
    extern __shared__ __nv_bfloat16 smem[];

    const int tid  = threadIdx.x;
    const int lane = tid & 31;
    const int w    = tid >> 5;
    const int wm   = (w >> 2) * 64;
    const int wn   = (w & 3) * 32;

    float acc[4][4][4];
#pragma unroll
    for (int im = 0; im < 4; im++)
#pragma unroll
        for (int in = 0; in < 4; in++)
#pragma unroll
            for (int q = 0; q < 4; q++)
                acc[im][in][q] = 0.0f;

    const uint32_t aS = (uint32_t)__cvta_generic_to_shared(smem);
    const int cr  = tid >> 2;
    const int cc8 = (tid & 3) * 8;

    const __nv_bfloat16* srcA_h = Xh + (size_t)(row0 + cr) * D_ + cc8;
    const __nv_bfloat16* srcA_l = Xl + (size_t)(row0 + cr) * D_ + cc8;
    const __nv_bfloat16* srcB_h = Wh + (size_t)(col0 + cr) * D_ + cc8;
    const __nv_bfloat16* srcB_l = Wl + (size_t)(col0 + cr) * D_ + cc8;
    const uint32_t dOff   = (uint32_t)(cr * GLDA + cc8) * 2;
    const uint32_t dRow64 = (uint32_t)(64 * GLDA) * 2;

#define ISSUE_COPY(sstage, k0v)                                                   \
    do {                                                                          \
        uint32_t db = aS + (uint32_t)((sstage) * 4 * GT) * 2 + dOff;              \
        cpasync16(db,                           srcA_h + (k0v));                  \
        cpasync16(db + dRow64,                  srcA_h + (k0v) + 64 * D_);        \
        cpasync16(db + (uint32_t)GT*2,          srcA_l + (k0v));                  \
        cpasync16(db + (uint32_t)GT*2 + dRow64, srcA_l + (k0v) + 64 * D_);        \
        cpasync16(db + (uint32_t)GT*4,          srcB_h + (k0v));                  \
        cpasync16(db + (uint32_t)GT*4 + dRow64, srcB_h + (k0v) + 64 * D_);        \
        cpasync16(db + (uint32_t)GT*6,          srcB_l + (k0v));                  \
        cpasync16(db + (uint32_t)GT*6 + dRow64, srcB_l + (k0v) + 64 * D_);        \
        asm volatile("cp.async.commit_group;");                                   \
    } while (0)

    ISSUE_COPY(0, 0);

    for (int kt = 0; kt < D_ / 32; kt++) {
        const int s = kt & 1;
        asm volatile("cp.async.wait_group 0;");
        __syncthreads();
        if (kt + 1 < D_ / 32)
            ISSUE_COPY(s ^ 1, (kt + 1) * 32);

        const uint32_t bAh = aS + (uint32_t)((s * 4 + 0) * GT) * 2;
        const uint32_t bAl = aS + (uint32_t)((s * 4 + 1) * GT) * 2;
        const uint32_t bBh = aS + (uint32_t)((s * 4 + 2) * GT) * 2;
        const uint32_t bBl = aS + (uint32_t)((s * 4 + 3) * GT) * 2;

#pragma unroll
        for (int kc = 0; kc < 2; kc++) {
            const uint32_t colb = (uint32_t)(kc * 16 + ((lane >> 4) << 3)) * 2;

            uint32_t bfh[4][2];
            uint32_t bfl[4][2];
#pragma unroll
            for (int np = 0; np < 2; np++) {
                uint32_t off = (uint32_t)((wn + np * 16 + (lane & 15)) * GLDA) * 2 + colb;
                uint32_t r4[4];
                ldsm4(r4, bBh + off);
                bfh[np * 2 + 0][0] = r4[0];
                bfh[np * 2 + 0][1] = r4[2];
                bfh[np * 2 + 1][0] = r4[1];
                bfh[np * 2 + 1][1] = r4[3];
                ldsm4(r4, bBl + off);
                bfl[np * 2 + 0][0] = r4[0];
                bfl[np * 2 + 0][1] = r4[2];
                bfl[np * 2 + 1][0] = r4[1];
                bfl[np * 2 + 1][1] = r4[3];
            }

#pragma unroll
            for (int im = 0; im < 4; im++) {
                uint32_t afh[4];
                uint32_t afl[4];
                uint32_t off = (uint32_t)((wm + im * 16 + (lane & 15)) * GLDA) * 2 + colb;
                ldsm4(afh, bAh + off);
                ldsm4(afl, bAl + off);
                // pass-major: consecutive mma target different accumulators;
                // per-accumulator order stays hh, hl, lh (K ascending).
#pragma unroll
                for (int in = 0; in < 4; in++)
                    mma16816(acc[im][in], afh, bfh[in]);
#pragma unroll
                for (int in = 0; in < 4; in++)
                    mma16816(acc[im][in], afh, bfl[in]);
#pragma unroll
                for (int in = 0; in < 4; in++)
                    mma16816(acc[im][in], afl, bfh[in]);
            }
        }
        // no trailing __syncthreads — next iteration's top barrier orders
        // all compute on stage s before any copy overwrites it.
    }
#undef ISSUE_COPY

    const int r_in = lane >> 2;
    const int c_in = (lane & 3) * 2;
#pragma unroll
    for (int im = 0; im < 4; im++) {
#pragma unroll
        for (int in = 0; in < 4; in++) {
            int rg = row0 + wm + im * 16 + r_in;
            int cg = col0 + wn + in * 8 + c_in;
            float b0 = bias[cg];
            float b1 = bias[cg + 1];
            float2 v0;
            float2 v1;
            v0.x = acc[im][in][0] + b0;
            v0.y = acc[im][in][1] + b1;
            v1.x = acc[im][in][2] + b0;
            v1.y = acc[im][in][3] + b1;
            if (MODE == 0) {
                *(float2*)(Yf + (size_t)rg * D_ + cg)       = v0;
                *(float2*)(Yf + (size_t)(rg + 8) * D_ + cg) = v1;
            } else {
                int hh = cg >> 6;
                int dd = cg & 63;
                int bb = rg >> 11;
                int ss = rg & (S_ - 1);
                size_t base = (((size_t)bb * H_ + hh) * S_ + ss) * DK_ + dd;
                __nv_bfloat162 h2, l2;
                split2(v0.x, v0.y, h2, l2);
                *(__nv_bfloat162*)(Yh + base) = h2;
                *(__nv_bfloat162*)(Yl + base) = l2;
                split2(v1.x, v1.y, h2, l2);
                *(__nv_bfloat162*)(Yh + base + 8 * DK_) = h2;
                *(__nv_bfloat162*)(Yl + base + 8 * DK_) = l2;
            }
        }
    }
}

// Fused Q/K/V projection: grid (24, 64); blockIdx.x>>3 selects the weight.
__global__ __launch_bounds__(256, 2) void gemm_qkv_kernel(const float* __restrict__ bq,
                                                          const float* __restrict__ bk,
                                                          const float* __restrict__ bv)
{
    const int which = blockIdx.x >> 3;
    const int col0  = (blockIdx.x & 7) * 128;
    const int row0  = blockIdx.y * 128;
    const __nv_bfloat16* Wh = (which == 0) ? g_wqh : (which == 1) ? g_wkh : g_wvh;
    const __nv_bfloat16* Wl = (which == 0) ? g_wql : (which == 1) ? g_wkl : g_wvl;
    const float* bias       = (which == 0) ? bq    : (which == 1) ? bk    : bv;
    __nv_bfloat16* Yh       = (which == 0) ? g_qh  : (which == 1) ? g_kh  : g_vh;
    __nv_bfloat16* Yl       = (which == 0) ? g_ql  : (which == 1) ? g_kl  : g_vl;
    gemm_tc<1>(g_xh, g_xl, Wh, Wl, bias, nullptr, Yh, Yl, row0, col0);
}

__global__ __launch_bounds__(256, 2) void gemm_o_kernel(const float* __restrict__ b,
                                                        float* __restrict__ out)
{
    gemm_tc<0>(g_oh, g_ol, g_woh, g_wol, b, out, nullptr, nullptr,
               blockIdx.y * 128, blockIdx.x * 128);
}

// ---------------------------------------------------------------------------
// Tensor-core flash attention. Changes vs round 14:
//  - __launch_bounds__(256, 2): 2 CTAs/SM (reg cap 128).
//  - Q fragments NOT register-resident: Q stays in smem (never overwritten),
//    fragments re-loaded via ldsm4 inside the QK^T t-loop (8 regs live, was 32).
// Math order identical -> bit-identical results.
// ---------------------------------------------------------------------------
#define LDQ   72
#define AQH   0
#define AQL   (128*LDQ)
#define AKV0  (2*128*LDQ)
#define KVARR (64*LDQ)
#define KVST  (4*KVARR)
#define ASM_BYTES ((AKV0 + 2*KVST) * 2)

__global__ __launch_bounds__(256, 2) void attn_kernel()
{
    extern __shared__ __nv_bfloat16 sm[];
    const int tid  = threadIdx.x;
    const int lane = tid & 31;
    const int w    = tid >> 5;
    const int bh   = blockIdx.y;
    const int qt   = gridDim.x - 1 - blockIdx.x;   // longest-first
    const int q0   = qt * 128;
    const int wrow = w * 16;

    const size_t hb = (size_t)bh * S_ * DK_;
    const uint32_t aS = (uint32_t)__cvta_generic_to_shared(sm);

    {
        int a = tid >> 7;
        int r = tid & 127;
        const __nv_bfloat16* src = (a ? g_ql : g_qh) + hb + (size_t)(q0 + r) * DK_;
        uint32_t dst = aS + (uint32_t)((a ? AQL : AQH) + r * LDQ) * 2;
#pragma unroll
        for (int c = 0; c < 8; c++)
            cpasync16(dst + c * 16, src + c * 8);
    }

    const int kv_a = tid >> 6;
    const int kv_r = tid & 63;
    const __nv_bfloat16* kv_src =
        ((kv_a == 0) ? g_kh : (kv_a == 1) ? g_kl : (kv_a == 2) ? g_vh : g_vl)
        + hb + (size_t)kv_r * DK_;
    const uint32_t kv_doff = (uint32_t)(AKV0 + kv_a * KVARR + kv_r * LDQ) * 2;

#define ISSUE_KV(kt_, st_)                                                        \
    do {                                                                          \
        const __nv_bfloat16* sp = kv_src + (size_t)(kt_) * 64 * DK_;              \
        uint32_t dst = aS + kv_doff + (uint32_t)((st_) * KVST) * 2;               \
        _Pragma("unroll")                                                         \
        for (int c = 0; c < 8; c++)                                               \
            cpasync16(dst + c * 16, sp + c * 8);                                  \
        asm volatile("cp.async.commit_group;");                                   \
    } while (0)

    ISSUE_KV(0, 0);

    const int ktmax = 2 * qt + 1;

    float o[8][4];
#pragma unroll
    for (int j = 0; j < 8; j++)
#pragma unroll
        for (int q = 0; q < 4; q++)
            o[j][q] = 0.0f;
    float m0 = -INFINITY, m1 = -INFINITY, l0 = 0.0f, l1 = 0.0f;

    for (int kt = 0; kt <= ktmax; kt++) {
        const int st = kt & 1;
        asm volatile("cp.async.wait_group 0;");
        __syncthreads();
        if (kt < ktmax)
            ISSUE_KV(kt + 1, st ^ 1);

        if (kt * 64 <= q0 + wrow + 15) {
            const uint32_t kvb = aS + (uint32_t)(AKV0 + st * KVST) * 2;

            float sf[8][4];
#pragma unroll
            for (int j = 0; j < 8; j++)
#pragma unroll
                for (int q = 0; q < 4; q++)
                    sf[j][q] = 0.0f;

#pragma unroll
            for (int t = 0; t < 4; t++) {
                const uint32_t colb = (uint32_t)(t * 16 + ((lane >> 4) << 3)) * 2;

                // Q fragments for this t-chunk (smem-resident, reload each use)
                uint32_t qfh[4];
                uint32_t qfl[4];
                {
                    uint32_t qoff = (uint32_t)((wrow + (lane & 15)) * LDQ) * 2 + colb;
                    ldsm4(qfh, aS + (uint32_t)AQH * 2 + qoff);
                    ldsm4(qfl, aS + (uint32_t)AQL * 2 + qoff);
                }
#pragma unroll
                for (int nt = 0; nt < 4; nt++) {
                    uint32_t off = kvb + (uint32_t)((nt * 16 + (lane & 15)) * LDQ) * 2 + colb;
                    uint32_t r4[4];
                    uint32_t kh0[2], kh1[2], kl0[2], kl1[2];
                    ldsm4(r4, off);
                    kh0[0] = r4[0]; kh0[1] = r4[2];
                    kh1[0] = r4[1]; kh1[1] = r4[3];
                    ldsm4(r4, off + (uint32_t)KVARR * 2);
                    kl0[0] = r4[0]; kl0[1] = r4[2];
                    kl1[0] = r4[1]; kl1[1] = r4[3];
                    mma16816(sf[nt * 2],     qfh, kh0);
                    mma16816(sf[nt * 2 + 1], qfh, kh1);
                    mma16816(sf[nt * 2],     qfh, kl0);
                    mma16816(sf[nt * 2 + 1], qfh, kl1);
                    mma16816(sf[nt * 2],     qfl, kh0);
                    mma16816(sf[nt * 2 + 1], qfl, kh1);
                }
            }

#pragma unroll
            for (int j = 0; j < 8; j++)
#pragma unroll
                for (int q = 0; q < 4; q++)
                    sf[j][q] *= 0.125f;

            const int r0g = q0 + wrow + (lane >> 2);
            const int r1g = r0g + 8;
            if (kt * 64 + 63 > q0 + wrow) {
                const int cbase = kt * 64 + 2 * (lane & 3);
#pragma unroll
                for (int j = 0; j < 8; j++) {
                    int c = cbase + 8 * j;
                    if (c     > r0g) sf[j][0] = -INFINITY;
                    if (c + 1 > r0g) sf[j][1] = -INFINITY;
                    if (c     > r1g) sf[j][2] = -INFINITY;
                    if (c + 1 > r1g) sf[j][3] = -INFINITY;
                }
            }

            float rm0 = -INFINITY, rm1 = -INFINITY;
#pragma unroll
            for (int j = 0; j < 8; j++) {
                rm0 = fmaxf(rm0, fmaxf(sf[j][0], sf[j][1]));
                rm1 = fmaxf(rm1, fmaxf(sf[j][2], sf[j][3]));
            }
            rm0 = fmaxf(rm0, __shfl_xor_sync(0xffffffffu, rm0, 1));
            rm0 = fmaxf(rm0, __shfl_xor_sync(0xffffffffu, rm0, 2));
            rm1 = fmaxf(rm1, __shfl_xor_sync(0xffffffffu, rm1, 1));
            rm1 = fmaxf(rm1, __shfl_xor_sync(0xffffffffu, rm1, 2));

            float mn0 = fmaxf(m0, rm0);
            float mn1 = fmaxf(m1, rm1);
            float rs0 = 0.0f, rs1 = 0.0f;
#pragma unroll
            for (int j = 0; j < 8; j++) {
                sf[j][0] = __expf(sf[j][0] - mn0);
                sf[j][1] = __expf(sf[j][1] - mn0);
                sf[j][2] = __expf(sf[j][2] - mn1);
                sf[j][3] = __expf(sf[j][3] - mn1);
                rs0 += sf[j][0] + sf[j][1];
                rs1 += sf[j][2] + sf[j][3];
            }
            rs0 += __shfl_xor_sync(0xffffffffu, rs0, 1);
            rs0 += __shfl_xor_sync(0xffffffffu, rs0, 2);
            rs1 += __shfl_xor_sync(0xffffffffu, rs1, 1);
            rs1 += __shfl_xor_sync(0xffffffffu, rs1, 2);

            float a0 = __expf(m0 - mn0);
            float a1 = __expf(m1 - mn1);
            l0 = l0 * a0 + rs0;
            l1 = l1 * a1 + rs1;
            m0 = mn0;
            m1 = mn1;
#pragma unroll
            for (int j = 0; j < 8; j++) {
                o[j][0] *= a0;
                o[j][1] *= a0;
                o[j][2] *= a1;
                o[j][3] *= a1;
            }

            uint32_t pah[4][4];
            uint32_t pal[4][4];
#pragma unroll
            for (int t = 0; t < 4; t++) {
                split_pack(sf[2*t][0],   sf[2*t][1],   pah[t][0], pal[t][0]);
                split_pack(sf[2*t][2],   sf[2*t][3],   pah[t][1], pal[t][1]);
                split_pack(sf[2*t+1][0], sf[2*t+1][1], pah[t][2], pal[t][2]);
                split_pack(sf[2*t+1][2], sf[2*t+1][3], pah[t][3], pal[t][3]);
            }

#pragma unroll
            for (int t = 0; t < 4; t++) {
#pragma unroll
                for (int dt = 0; dt < 4; dt++) {
                    uint32_t off = kvb
                        + (uint32_t)((t * 16 + ((lane & 16) >> 1) + (lane & 7)) * LDQ
                                     + dt * 16 + (lane & 8)) * 2;
                    uint32_t r4[4];
                    uint32_t vh0[2], vh1[2], vl0[2], vl1[2];
                    ldsm4t(r4, off + (uint32_t)(2 * KVARR) * 2);
                    vh0[0] = r4[0]; vh0[1] = r4[2];
                    vh1[0] = r4[1]; vh1[1] = r4[3];
                    ldsm4t(r4, off + (uint32_t)(3 * KVARR) * 2);
                    vl0[0] = r4[0]; vl0[1] = r4[2];
                    vl1[0] = r4[1]; vl1[1] = r4[3];
                    mma16816(o[dt * 2],     pah[t], vh0);
                    mma16816(o[dt * 2 + 1], pah[t], vh1);
                    mma16816(o[dt * 2],     pah[t], vl0);
                    mma16816(o[dt * 2 + 1], pah[t], vl1);
                    mma16816(o[dt * 2],     pal[t], vh0);
                    mma16816(o[dt * 2 + 1], pal[t], vh1);
                }
            }
        }
    }
#undef ISSUE_KV

    const float in0 = 1.0f / l0;
    const float in1 = 1.0f / l1;
    const int r0 = q0 + wrow + (lane >> 2);
    const int bb = bh >> 4;
    const int hh = bh & 15;
#pragma unroll
    for (int j = 0; j < 8; j++) {
        int d = hh * 64 + j * 8 + 2 * (lane & 3);
        size_t i0 = ((size_t)bb * S_ + r0) * D_ + d;
        size_t i1 = i0 + (size_t)8 * D_;
        __nv_bfloat162 h2, l2;
        split2(o[j][0] * in0, o[j][1] * in0, h2, l2);
        *(__nv_bfloat162*)(g_oh + i0) = h2;
        *(__nv_bfloat162*)(g_ol + i0) = l2;
        split2(o[j][2] * in1, o[j][3] * in1, h2, l2);
        *(__nv_bfloat162*)(g_oh + i1) = h2;
        *(__nv_bfloat162*)(g_ol + i1) = l2;
    }
}

// ---------------------------------------------------------------------------
extern "C" void kernel_launch(void* const* d_in, const int* in_sizes, int n_in,
                              void* d_out, int out_size)
{
    const float* x  = (const float*)d_in[0];
    const float* Wq = (const float*)d_in[1];
    const float* bq = (const float*)d_in[2];
    const float* Wk = (const float*)d_in[3];
    const float* bk = (const float*)d_in[4];
    const float* Wv = (const float*)d_in[5];
    const float* bv = (const float*)d_in[6];
    const float* Wo = (const float*)d_in[7];
    const float* bo = (const float*)d_in[8];
    float* out = (float*)d_out;

    static int attr_set = 0;
    if (!attr_set) {
        cudaFuncSetAttribute(gemm_qkv_kernel, cudaFuncAttributeMaxDynamicSharedMemorySize, GSM);
        cudaFuncSetAttribute(gemm_o_kernel,   cudaFuncAttributeMaxDynamicSharedMemorySize, GSM);
        cudaFuncSetAttribute(attn_kernel,     cudaFuncAttributeMaxDynamicSharedMemorySize, ASM_BYTES);
        attr_set = 1;
    }

    pack_x_kernel <<<(M_ * D_) / 1024, 256>>>(x);                   // 0
    pack_w4_kernel<<<4 * (D_ * D_) / 1024, 256>>>(Wq, Wk, Wv, Wo);  // 1

    gemm_qkv_kernel<<<dim3(24, 64), 256, GSM>>>(bq, bk, bv);        // 2

    attn_kernel<<<dim3(S_ / 128, B_ * H_), 256, ASM_BYTES>>>();     // 3  <- ncu target

    gemm_o_kernel<<<dim3(8, 64), 256, GSM>>>(bo, out);              // 4
}

// round 17
// speedup vs baseline: 1.4638x; 1.0718x over previous
#include <cuda_runtime.h>
#include <cuda_bf16.h>
#include <cstdint>
#include <math.h>

#define B_  4
#define S_  2048
#define D_  1024
#define H_  16
#define DK_ 64
#define M_  (B_*S_)

// ---------------------------------------------------------------------------
// Scratch (__device__ globals). All tensors split bf16 hi + lo residual.
// ---------------------------------------------------------------------------
__device__ __nv_bfloat16 g_xh[(size_t)M_*D_];
__device__ __nv_bfloat16 g_xl[(size_t)M_*D_];
__device__ __nv_bfloat16 g_qh[(size_t)M_*D_];
__device__ __nv_bfloat16 g_ql[(size_t)M_*D_];
__device__ __nv_bfloat16 g_kh[(size_t)M_*D_];
__device__ __nv_bfloat16 g_kl[(size_t)M_*D_];
__device__ __nv_bfloat16 g_vh[(size_t)M_*D_];
__device__ __nv_bfloat16 g_vl[(size_t)M_*D_];
__device__ __nv_bfloat16 g_oh[(size_t)M_*D_];
__device__ __nv_bfloat16 g_ol[(size_t)M_*D_];

__device__ __nv_bfloat16 g_wqh[(size_t)D_*D_], g_wql[(size_t)D_*D_];
__device__ __nv_bfloat16 g_wkh[(size_t)D_*D_], g_wkl[(size_t)D_*D_];
__device__ __nv_bfloat16 g_wvh[(size_t)D_*D_], g_wvl[(size_t)D_*D_];
__device__ __nv_bfloat16 g_woh[(size_t)D_*D_], g_wol[(size_t)D_*D_];

// ---------------------------------------------------------------------------
// helpers
// ---------------------------------------------------------------------------
__device__ __forceinline__ void split2(float a, float b,
                                       __nv_bfloat162& h2, __nv_bfloat162& l2)
{
    h2.x = __float2bfloat16(a);
    h2.y = __float2bfloat16(b);
    l2.x = __float2bfloat16(a - __bfloat162float(h2.x));
    l2.y = __float2bfloat16(b - __bfloat162float(h2.y));
}

__device__ __forceinline__ void split_pack(float a, float b, uint32_t& hi, uint32_t& lo)
{
    __nv_bfloat162 h2, l2;
    split2(a, b, h2, l2);
    hi = *(uint32_t*)&h2;
    lo = *(uint32_t*)&l2;
}

__device__ __forceinline__ void ldsm4(uint32_t* r, uint32_t addr)
{
    asm volatile("ldmatrix.sync.aligned.m8n8.x4.shared.b16 {%0,%1,%2,%3}, [%4];"
        : "=r"(r[0]), "=r"(r[1]), "=r"(r[2]), "=r"(r[3]) : "r"(addr));
}

__device__ __forceinline__ void ldsm4t(uint32_t* r, uint32_t addr)
{
    asm volatile("ldmatrix.sync.aligned.m8n8.x4.trans.shared.b16 {%0,%1,%2,%3}, [%4];"
        : "=r"(r[0]), "=r"(r[1]), "=r"(r[2]), "=r"(r[3]) : "r"(addr));
}

__device__ __forceinline__ void mma16816(float* c, const uint32_t* a, const uint32_t* b)
{
    asm volatile("mma.sync.aligned.m16n8k16.row.col.f32.bf16.bf16.f32 "
        "{%0,%1,%2,%3}, {%4,%5,%6,%7}, {%8,%9}, {%0,%1,%2,%3};"
        : "+f"(c[0]), "+f"(c[1]), "+f"(c[2]), "+f"(c[3])
        : "r"(a[0]), "r"(a[1]), "r"(a[2]), "r"(a[3]), "r"(b[0]), "r"(b[1]));
}

__device__ __forceinline__ void cpasync16(uint32_t dst, const void* src)
{
    asm volatile("cp.async.cg.shared.global [%0], [%1], 16;" :: "r"(dst), "l"(src));
}

// ---------------------------------------------------------------------------
// Pack kernels: fp32 -> bf16 hi + lo
// ---------------------------------------------------------------------------
__device__ __forceinline__ void pack_body(const float* __restrict__ src,
                                          __nv_bfloat16* __restrict__ hi,
                                          __nv_bfloat16* __restrict__ lo,
                                          int blk)
{
    int i = (blk * 256 + threadIdx.x) * 4;
    float4 v = *(const float4*)(src + i);
    __nv_bfloat162 h0, l0, h1, l1;
    split2(v.x, v.y, h0, l0);
    split2(v.z, v.w, h1, l1);
    *(__nv_bfloat162*)(hi + i)     = h0;
    *(__nv_bfloat162*)(hi + i + 2) = h1;
    *(__nv_bfloat162*)(lo + i)     = l0;
    *(__nv_bfloat162*)(lo + i + 2) = l1;
}

__global__ __launch_bounds__(256) void pack_x_kernel(const float* __restrict__ s)
{ pack_body(s, g_xh, g_xl, blockIdx.x); }

// packs Wq, Wk, Wv, Wo in one launch: 1024 blocks each (4096 total)
__global__ __launch_bounds__(256) void pack_w4_kernel(const float* __restrict__ wq,
                                                      const float* __restrict__ wk,
                                                      const float* __restrict__ wv,
                                                      const float* __restrict__ wo)
{
    int which = blockIdx.x >> 10;
    int blk   = blockIdx.x & 1023;
    const float* src = (which == 0) ? wq : (which == 1) ? wk : (which == 2) ? wv : wo;
    __nv_bfloat16* hi = (which == 0) ? g_wqh : (which == 1) ? g_wkh
                       : (which == 2) ? g_wvh : g_woh;
    __nv_bfloat16* lo = (which == 0) ? g_wql : (which == 1) ? g_wkl
                       : (which == 2) ? g_wvl : g_wol;
    pack_body(src, hi, lo, blk);
}

// ---------------------------------------------------------------------------
// Tensor-core GEMM (split bf16, 3-pass), BK=32, XOR-swizzled 64B-row smem
// layout (chunk c at position c ^ ((row>>1)&3)) -> 32KB/stage, 3 stages
// (96KB), wait_group 1: copy(kt) gets two compute-tiles of latency budget.
// 2 CTAs/SM (reg cap 128), one barrier per k-tile.
// ---------------------------------------------------------------------------
#define GARRB 8192u                 // bytes per array (128 rows x 64B)
#define GSTGB 32768u                // bytes per stage (4 arrays)
#define GSM3  (3 * 32768)           // 98304 dynamic smem bytes
#define GNKT  32                    // 32 x 32-half K tiles

template<int MODE>
__device__ __forceinline__ void gemm_tc(const __nv_bfloat16* __restrict__ Xh,
                                        const __nv_bfloat16* __restrict__ Xl,
                                        const __nv_bfloat16* __restrict__ Wh,
                                        const __nv_bfloat16* __restrict__ Wl,
                                        const float* __restrict__ bias,
                                        float* __restrict__ Yf,
                                        __nv_bfloat16* __restrict__ Yh,
                                        __nv_bfloat16* __restrict__ Yl,
                                        int row0, int col0)
{
    extern __shared__ __nv_bfloat16 smem[];

    const int tid  = threadIdx.x;
    const int lane = tid & 31;
    const int w    = tid >> 5;
    const int wm   = (w >> 2) * 64;
    const int wn   = (w & 3) * 32;

    float acc[4][4][4];
#pragma unroll
    for (int im = 0; im < 4; im++)
#pragma unroll
        for (int in = 0; in < 4; in++)
#pragma unroll
            for (int q = 0; q < 4; q++)
                acc[im][in][q] = 0.0f;

    const uint32_t aS = (uint32_t)__cvta_generic_to_shared(smem);

    // ---- copy mapping: cr = row (0..63, +64 pair), ck = 16B chunk (0..3) ----
    const int cr = tid >> 2;
    const int ck = tid & 3;
    const int csw = (cr >> 1) & 3;                 // same for cr and cr+64
    const uint32_t dOff0 = (uint32_t)(cr * 64 + ((ck ^ csw) << 4));
    const uint32_t dOff1 = dOff0 + 64 * 64;

    const __nv_bfloat16* srcA_h = Xh + (size_t)(row0 + cr) * D_ + ck * 8;
    const __nv_bfloat16* srcA_l = Xl + (size_t)(row0 + cr) * D_ + ck * 8;
    const __nv_bfloat16* srcB_h = Wh + (size_t)(col0 + cr) * D_ + ck * 8;
    const __nv_bfloat16* srcB_l = Wl + (size_t)(col0 + cr) * D_ + ck * 8;

#define ISSUE_COPY(stg, k0v)                                                   \
    do {                                                                       \
        uint32_t db = aS + (uint32_t)(stg) * GSTGB;                            \
        cpasync16(db + dOff0,              srcA_h + (k0v));                    \
        cpasync16(db + dOff1,              srcA_h + (k0v) + 64 * D_);          \
        cpasync16(db + GARRB + dOff0,      srcA_l + (k0v));                    \
        cpasync16(db + GARRB + dOff1,      srcA_l + (k0v) + 64 * D_);          \
        cpasync16(db + 2 * GARRB + dOff0,  srcB_h + (k0v));                    \
        cpasync16(db + 2 * GARRB + dOff1,  srcB_h + (k0v) + 64 * D_);          \
        cpasync16(db + 3 * GARRB + dOff0,  srcB_l + (k0v));                    \
        cpasync16(db + 3 * GARRB + dOff1,  srcB_l + (k0v) + 64 * D_);          \
        asm volatile("cp.async.commit_group;");                                \
    } while (0)

    ISSUE_COPY(0, 0);
    ISSUE_COPY(1, 32);

    // ldsm swizzle term reduces to a per-thread constant:
    // (row>>1)&3 with row = (mult of 16) + (lane&15)  ==  ((lane&15)>>1)&3
    const uint32_t lsw = (uint32_t)(((lane & 15) >> 1) & 3);
    const uint32_t lrow = (uint32_t)(lane & 15);
    const uint32_t lhi  = (uint32_t)(lane >> 4);    // 0/1: second 16B chunk

    for (int kt = 0; kt < GNKT; kt++) {
        const int s = kt % 3;
        if (kt < GNKT - 1) asm volatile("cp.async.wait_group 1;");
        else               asm volatile("cp.async.wait_group 0;");
        __syncthreads();
        if (kt + 2 < GNKT)
            ISSUE_COPY((kt + 2) % 3, (kt + 2) * 32);

        const uint32_t bS  = aS + (uint32_t)s * GSTGB;
        const uint32_t bAh = bS;
        const uint32_t bAl = bS + GARRB;
        const uint32_t bBh = bS + 2 * GARRB;
        const uint32_t bBl = bS + 3 * GARRB;

#pragma unroll
        for (int kc = 0; kc < 2; kc++) {
            const uint32_t chunk = (uint32_t)(kc * 2) + lhi;
            const uint32_t colb  = ((chunk ^ lsw) << 4);

            uint32_t bfh[4][2];
            uint32_t bfl[4][2];
#pragma unroll
            for (int np = 0; np < 2; np++) {
                uint32_t off = (uint32_t)((wn + np * 16) + lrow) * 64 + colb;
                uint32_t r4[4];
                ldsm4(r4, bBh + off);
                bfh[np * 2 + 0][0] = r4[0];
                bfh[np * 2 + 0][1] = r4[2];
                bfh[np * 2 + 1][0] = r4[1];
                bfh[np * 2 + 1][1] = r4[3];
                ldsm4(r4, bBl + off);
                bfl[np * 2 + 0][0] = r4[0];
                bfl[np * 2 + 0][1] = r4[2];
                bfl[np * 2 + 1][0] = r4[1];
                bfl[np * 2 + 1][1] = r4[3];
            }

#pragma unroll
            for (int im = 0; im < 4; im++) {
                uint32_t afh[4];
                uint32_t afl[4];
                uint32_t off = (uint32_t)((wm + im * 16) + lrow) * 64 + colb;
                ldsm4(afh, bAh + off);
                ldsm4(afl, bAl + off);
                // pass-major; per-accumulator order hh, hl, lh (K ascending).
#pragma unroll
                for (int in = 0; in < 4; in++)
                    mma16816(acc[im][in], afh, bfh[in]);
#pragma unroll
                for (int in = 0; in < 4; in++)
                    mma16816(acc[im][in], afh, bfl[in]);
#pragma unroll
                for (int in = 0; in < 4; in++)
                    mma16816(acc[im][in], afl, bfh[in]);
            }
        }
        // no trailing __syncthreads — the next iteration's top barrier orders
        // all compute on a stage before any copy overwrites it.
    }
#undef ISSUE_COPY

    const int r_in = lane >> 2;
    const int c_in = (lane & 3) * 2;
#pragma unroll
    for (int im = 0; im < 4; im++) {
#pragma unroll
        for (int in = 0; in < 4; in++) {
            int rg = row0 + wm + im * 16 + r_in;
            int cg = col0 + wn + in * 8 + c_in;
            float b0 = bias[cg];
            float b1 = bias[cg + 1];
            float2 v0;
            float2 v1;
            v0.x = acc[im][in][0] + b0;
            v0.y = acc[im][in][1] + b1;
            v1.x = acc[im][in][2] + b0;
            v1.y = acc[im][in][3] + b1;
            if (MODE == 0) {
                *(float2*)(Yf + (size_t)rg * D_ + cg)       = v0;
                *(float2*)(Yf + (size_t)(rg + 8) * D_ + cg) = v1;
            } else {
                int hh = cg >> 6;
                int dd = cg & 63;
                int bb = rg >> 11;
                int ss = rg & (S_ - 1);
                size_t base = (((size_t)bb * H_ + hh) * S_ + ss) * DK_ + dd;
                __nv_bfloat162 h2, l2;
                split2(v0.x, v0.y, h2, l2);
                *(__nv_bfloat162*)(Yh + base) = h2;
                *(__nv_bfloat162*)(Yl + base) = l2;
                split2(v1.x, v1.y, h2, l2);
                *(__nv_bfloat162*)(Yh + base + 8 * DK_) = h2;
                *(__nv_bfloat162*)(Yl + base + 8 * DK_) = l2;
            }
        }
    }
}

// Fused Q/K/V projection: grid (24, 64); blockIdx.x>>3 selects the weight.
__global__ __launch_bounds__(256, 2) void gemm_qkv_kernel(const float* __restrict__ bq,
                                                          const float* __restrict__ bk,
                                                          const float* __restrict__ bv)
{
    const int which = blockIdx.x >> 3;
    const int col0  = (blockIdx.x & 7) * 128;
    const int row0  = blockIdx.y * 128;
    const __nv_bfloat16* Wh = (which == 0) ? g_wqh : (which == 1) ? g_wkh : g_wvh;
    const __nv_bfloat16* Wl = (which == 0) ? g_wql : (which == 1) ? g_wkl : g_wvl;
    const float* bias       = (which == 0) ? bq    : (which == 1) ? bk    : bv;
    __nv_bfloat16* Yh       = (which == 0) ? g_qh  : (which == 1) ? g_kh  : g_vh;
    __nv_bfloat16* Yl       = (which == 0) ? g_ql  : (which == 1) ? g_kl  : g_vl;
    gemm_tc<1>(g_xh, g_xl, Wh, Wl, bias, nullptr, Yh, Yl, row0, col0);
}

__global__ __launch_bounds__(256, 2) void gemm_o_kernel(const float* __restrict__ b,
                                                        float* __restrict__ out)
{
    gemm_tc<0>(g_oh, g_ol, g_woh, g_wol, b, out, nullptr, nullptr,
               blockIdx.y * 128, blockIdx.x * 128);
}

// ---------------------------------------------------------------------------
// Tensor-core flash attention — unchanged from round 15 (2 CTAs/SM,
// smem-resident Q fragments, longest-first scheduling).
// ---------------------------------------------------------------------------
#define LDQ   72
#define AQH   0
#define AQL   (128*LDQ)
#define AKV0  (2*128*LDQ)
#define KVARR (64*LDQ)
#define KVST  (4*KVARR)
#define ASM_BYTES ((AKV0 + 2*KVST) * 2)

__global__ __launch_bounds__(256, 2) void attn_kernel()
{
    extern __shared__ __nv_bfloat16 sm[];
    const int tid  = threadIdx.x;
    const int lane = tid & 31;
    const int w    = tid >> 5;
    const int bh   = blockIdx.y;
    const int qt   = gridDim.x - 1 - blockIdx.x;   // longest-first
    const int q0   = qt * 128;
    const int wrow = w * 16;

    const size_t hb = (size_t)bh * S_ * DK_;
    const uint32_t aS = (uint32_t)__cvta_generic_to_shared(sm);

    {
        int a = tid >> 7;
        int r = tid & 127;
        const __nv_bfloat16* src = (a ? g_ql : g_qh) + hb + (size_t)(q0 + r) * DK_;
        uint32_t dst = aS + (uint32_t)((a ? AQL : AQH) + r * LDQ) * 2;
#pragma unroll
        for (int c = 0; c < 8; c++)
            cpasync16(dst + c * 16, src + c * 8);
    }

    const int kv_a = tid >> 6;
    const int kv_r = tid & 63;
    const __nv_bfloat16* kv_src =
        ((kv_a == 0) ? g_kh : (kv_a == 1) ? g_kl : (kv_a == 2) ? g_vh : g_vl)
        + hb + (size_t)kv_r * DK_;
    const uint32_t kv_doff = (uint32_t)(AKV0 + kv_a * KVARR + kv_r * LDQ) * 2;

#define ISSUE_KV(kt_, st_)                                                        \
    do {                                                                          \
        const __nv_bfloat16* sp = kv_src + (size_t)(kt_) * 64 * DK_;              \
        uint32_t dst = aS + kv_doff + (uint32_t)((st_) * KVST) * 2;               \
        _Pragma("unroll")                                                         \
        for (int c = 0; c < 8; c++)                                               \
            cpasync16(dst + c * 16, sp + c * 8);                                  \
        asm volatile("cp.async.commit_group;");                                   \
    } while (0)

    ISSUE_KV(0, 0);

    const int ktmax = 2 * qt + 1;

    float o[8][4];
#pragma unroll
    for (int j = 0; j < 8; j++)
#pragma unroll
        for (int q = 0; q < 4; q++)
            o[j][q] = 0.0f;
    float m0 = -INFINITY, m1 = -INFINITY, l0 = 0.0f, l1 = 0.0f;

    for (int kt = 0; kt <= ktmax; kt++) {
        const int st = kt & 1;
        asm volatile("cp.async.wait_group 0;");
        __syncthreads();
        if (kt < ktmax)
            ISSUE_KV(kt + 1, st ^ 1);

        if (kt * 64 <= q0 + wrow + 15) {
            const uint32_t kvb = aS + (uint32_t)(AKV0 + st * KVST) * 2;

            float sf[8][4];
#pragma unroll
            for (int j = 0; j < 8; j++)
#pragma unroll
                for (int q = 0; q < 4; q++)
                    sf[j][q] = 0.0f;

#pragma unroll
            for (int t = 0; t < 4; t++) {
                const uint32_t colb = (uint32_t)(t * 16 + ((lane >> 4) << 3)) * 2;

                uint32_t qfh[4];
                uint32_t qfl[4];
                {
                    uint32_t qoff = (uint32_t)((wrow + (lane & 15)) * LDQ) * 2 + colb;
                    ldsm4(qfh, aS + (uint32_t)AQH * 2 + qoff);
                    ldsm4(qfl, aS + (uint32_t)AQL * 2 + qoff);
                }
#pragma unroll
                for (int nt = 0; nt < 4; nt++) {
                    uint32_t off = kvb + (uint32_t)((nt * 16 + (lane & 15)) * LDQ) * 2 + colb;
                    uint32_t r4[4];
                    uint32_t kh0[2], kh1[2], kl0[2], kl1[2];
                    ldsm4(r4, off);
                    kh0[0] = r4[0]; kh0[1] = r4[2];
                    kh1[0] = r4[1]; kh1[1] = r4[3];
                    ldsm4(r4, off + (uint32_t)KVARR * 2);
                    kl0[0] = r4[0]; kl0[1] = r4[2];
                    kl1[0] = r4[1]; kl1[1] = r4[3];
                    mma16816(sf[nt * 2],     qfh, kh0);
                    mma16816(sf[nt * 2 + 1], qfh, kh1);
                    mma16816(sf[nt * 2],     qfh, kl0);
                    mma16816(sf[nt * 2 + 1], qfh, kl1);
                    mma16816(sf[nt * 2],     qfl, kh0);
                    mma16816(sf[nt * 2 + 1], qfl, kh1);
                }
            }

#pragma unroll
            for (int j = 0; j < 8; j++)
#pragma unroll
                for (int q = 0; q < 4; q++)
                    sf[j][q] *= 0.125f;

            const int r0g = q0 + wrow + (lane >> 2);
            const int r1g = r0g + 8;
            if (kt * 64 + 63 > q0 + wrow) {
                const int cbase = kt * 64 + 2 * (lane & 3);
#pragma unroll
                for (int j = 0; j < 8; j++) {
                    int c = cbase + 8 * j;
                    if (c     > r0g) sf[j][0] = -INFINITY;
                    if (c + 1 > r0g) sf[j][1] = -INFINITY;
                    if (c     > r1g) sf[j][2] = -INFINITY;
                    if (c + 1 > r1g) sf[j][3] = -INFINITY;
                }
            }

            float rm0 = -INFINITY, rm1 = -INFINITY;
#pragma unroll
            for (int j = 0; j < 8; j++) {
                rm0 = fmaxf(rm0, fmaxf(sf[j][0], sf[j][1]));
                rm1 = fmaxf(rm1, fmaxf(sf[j][2], sf[j][3]));
            }
            rm0 = fmaxf(rm0, __shfl_xor_sync(0xffffffffu, rm0, 1));
            rm0 = fmaxf(rm0, __shfl_xor_sync(0xffffffffu, rm0, 2));
            rm1 = fmaxf(rm1, __shfl_xor_sync(0xffffffffu, rm1, 1));
            rm1 = fmaxf(rm1, __shfl_xor_sync(0xffffffffu, rm1, 2));

            float mn0 = fmaxf(m0, rm0);
            float mn1 = fmaxf(m1, rm1);
            float rs0 = 0.0f, rs1 = 0.0f;
#pragma unroll
            for (int j = 0; j < 8; j++) {
                sf[j][0] = __expf(sf[j][0] - mn0);
                sf[j][1] = __expf(sf[j][1] - mn0);
                sf[j][2] = __expf(sf[j][2] - mn1);
                sf[j][3] = __expf(sf[j][3] - mn1);
                rs0 += sf[j][0] + sf[j][1];
                rs1 += sf[j][2] + sf[j][3];
            }
            rs0 += __shfl_xor_sync(0xffffffffu, rs0, 1);
            rs0 += __shfl_xor_sync(0xffffffffu, rs0, 2);
            rs1 += __shfl_xor_sync(0xffffffffu, rs1, 1);
            rs1 += __shfl_xor_sync(0xffffffffu, rs1, 2);

            float a0 = __expf(m0 - mn0);
            float a1 = __expf(m1 - mn1);
            l0 = l0 * a0 + rs0;
            l1 = l1 * a1 + rs1;
            m0 = mn0;
            m1 = mn1;
#pragma unroll
            for (int j = 0; j < 8; j++) {
                o[j][0] *= a0;
                o[j][1] *= a0;
                o[j][2] *= a1;
                o[j][3] *= a1;
            }

            uint32_t pah[4][4];
            uint32_t pal[4][4];
#pragma unroll
            for (int t = 0; t < 4; t++) {
                split_pack(sf[2*t][0],   sf[2*t][1],   pah[t][0], pal[t][0]);
                split_pack(sf[2*t][2],   sf[2*t][3],   pah[t][1], pal[t][1]);
                split_pack(sf[2*t+1][0], sf[2*t+1][1], pah[t][2], pal[t][2]);
                split_pack(sf[2*t+1][2], sf[2*t+1][3], pah[t][3], pal[t][3]);
            }

#pragma unroll
            for (int t = 0; t < 4; t++) {
#pragma unroll
                for (int dt = 0; dt < 4; dt++) {
                    uint32_t off = kvb
                        + (uint32_t)((t * 16 + ((lane & 16) >> 1) + (lane & 7)) * LDQ
                                     + dt * 16 + (lane & 8)) * 2;
                    uint32_t r4[4];
                    uint32_t vh0[2], vh1[2], vl0[2], vl1[2];
                    ldsm4t(r4, off + (uint32_t)(2 * KVARR) * 2);
                    vh0[0] = r4[0]; vh0[1] = r4[2];
                    vh1[0] = r4[1]; vh1[1] = r4[3];
                    ldsm4t(r4, off + (uint32_t)(3 * KVARR) * 2);
                    vl0[0] = r4[0]; vl0[1] = r4[2];
                    vl1[0] = r4[1]; vl1[1] = r4[3];
                    mma16816(o[dt * 2],     pah[t], vh0);
                    mma16816(o[dt * 2 + 1], pah[t], vh1);
                    mma16816(o[dt * 2],     pah[t], vl0);
                    mma16816(o[dt * 2 + 1], pah[t], vl1);
                    mma16816(o[dt * 2],     pal[t], vh0);
                    mma16816(o[dt * 2 + 1], pal[t], vh1);
                }
            }
        }
    }
#undef ISSUE_KV

    const float in0 = 1.0f / l0;
    const float in1 = 1.0f / l1;
    const int r0 = q0 + wrow + (lane >> 2);
    const int bb = bh >> 4;
    const int hh = bh & 15;
#pragma unroll
    for (int j = 0; j < 8; j++) {
        int d = hh * 64 + j * 8 + 2 * (lane & 3);
        size_t i0 = ((size_t)bb * S_ + r0) * D_ + d;
        size_t i1 = i0 + (size_t)8 * D_;
        __nv_bfloat162 h2, l2;
        split2(o[j][0] * in0, o[j][1] * in0, h2, l2);
        *(__nv_bfloat162*)(g_oh + i0) = h2;
        *(__nv_bfloat162*)(g_ol + i0) = l2;
        split2(o[j][2] * in1, o[j][3] * in1, h2, l2);
        *(__nv_bfloat162*)(g_oh + i1) = h2;
        *(__nv_bfloat162*)(g_ol + i1) = l2;
    }
}

// ---------------------------------------------------------------------------
extern "C" void kernel_launch(void* const* d_in, const int* in_sizes, int n_in,
                              void* d_out, int out_size)
{
    const float* x  = (const float*)d_in[0];
    const float* Wq = (const float*)d_in[1];
    const float* bq = (const float*)d_in[2];
    const float* Wk = (const float*)d_in[3];
    const float* bk = (const float*)d_in[4];
    const float* Wv = (const float*)d_in[5];
    const float* bv = (const float*)d_in[6];
    const float* Wo = (const float*)d_in[7];
    const float* bo = (const float*)d_in[8];
    float* out = (float*)d_out;

    static int attr_set = 0;
    if (!attr_set) {
        cudaFuncSetAttribute(gemm_qkv_kernel, cudaFuncAttributeMaxDynamicSharedMemorySize, GSM3);
        cudaFuncSetAttribute(gemm_o_kernel,   cudaFuncAttributeMaxDynamicSharedMemorySize, GSM3);
        cudaFuncSetAttribute(attn_kernel,     cudaFuncAttributeMaxDynamicSharedMemorySize, ASM_BYTES);
        attr_set = 1;
    }

    pack_x_kernel <<<(M_ * D_) / 1024, 256>>>(x);                   // 0
    pack_w4_kernel<<<4 * (D_ * D_) / 1024, 256>>>(Wq, Wk, Wv, Wo);  // 1

    gemm_qkv_kernel<<<dim3(24, 64), 256, GSM3>>>(bq, bk, bv);       // 2

    attn_kernel<<<dim3(S_ / 128, B_ * H_), 256, ASM_BYTES>>>();     // 3

    gemm_o_kernel<<<dim3(8, 64), 256, GSM3>>>(bo, out);             // 4
}